// round 2
// baseline (speedup 1.0000x reference)
#include <cuda_runtime.h>
#include <cstdint>
#include <cstddef>

// ============================================================================
// VAE_gamma: encoder (3 relu GEMMs) -> 2 softplus heads -> Marsaglia-Tsang
// gamma rejection sampler (JAX threefry RNG, key 42, PARTITIONABLE mode)
// -> decoder (3 relu GEMMs + final GEMM) -> softplus split outputs.
// All math fp32 to keep accept/reject decisions stable vs the reference.
// ============================================================================

#define BATCHN   8192
#define LATENT   64
#define KROUNDS  24

static_assert(BATCHN * LATENT == 524288, "");
#define GAMMA_N  524288u      // elements per round

// ---------------------------------------------------------------------------
// Scratch (static __device__ arrays: allowed; no cudaMalloc anywhere)
// ---------------------------------------------------------------------------
__device__ float g_buf0[8192 * 2048];
__device__ float g_buf1[8192 * 2048];
__device__ float g_dec [8192 * 4096];
__device__ float g_preA[8192 * 64];
__device__ float g_preB[8192 * 64];
__device__ float g_z   [8192 * 64];

// ---------------------------------------------------------------------------
// Threefry-2x32 (matches JAX). constexpr version for compile-time split keys.
// ---------------------------------------------------------------------------
constexpr unsigned rotlc(unsigned x, int r) { return (x << r) | (x >> (32 - r)); }

constexpr unsigned long long tf_const(unsigned k0, unsigned k1,
                                      unsigned x0, unsigned x1) {
    unsigned kx = k0 ^ k1 ^ 0x1BD11BDAu;
    unsigned ks[3] = {k0, k1, kx};
    const int R0[4] = {13, 15, 26, 6};
    const int R1[4] = {17, 29, 16, 24};
    x0 += k0; x1 += k1;
    for (int i = 0; i < 5; i++) {
        const int* rr = (i % 2 == 0) ? R0 : R1;
        for (int j = 0; j < 4; j++) { x0 += x1; x1 = rotlc(x1, rr[j]); x1 ^= x0; }
        x0 += ks[(i + 1) % 3];
        x1 += ks[(i + 2) % 3] + (unsigned)(i + 1);
    }
    return ((unsigned long long)x0 << 32) | x1;
}

// jax.random.key(42) -> key = (0, 42).
// PARTITIONABLE split (fold-like): subkey_i = threefry(key, (hi64_i, lo64_i))
// over a 64-bit iota; for num=2: k_eps = tf(key,(0,0)), k_u = tf(key,(0,1)).
constexpr unsigned long long SPN = tf_const(0u, 42u, 0u, 0u);
constexpr unsigned long long SPU = tf_const(0u, 42u, 0u, 1u);
constexpr unsigned KEY_N0 = (unsigned)(SPN >> 32);
constexpr unsigned KEY_N1 = (unsigned)(SPN & 0xFFFFFFFFu);
constexpr unsigned KEY_U0 = (unsigned)(SPU >> 32);
constexpr unsigned KEY_U1 = (unsigned)(SPU & 0xFFFFFFFFu);

__device__ __forceinline__ uint32_t rotl32(uint32_t x, int r) {
    return __funnelshift_l(x, x, r);
}

__device__ __forceinline__ void tf2x32(uint32_t k0, uint32_t k1,
                                       uint32_t x0, uint32_t x1,
                                       uint32_t& y0, uint32_t& y1) {
    uint32_t kx = k0 ^ k1 ^ 0x1BD11BDAu;
    x0 += k0; x1 += k1;
#define TF_RND(r) { x0 += x1; x1 = rotl32(x1, r); x1 ^= x0; }
    TF_RND(13) TF_RND(15) TF_RND(26) TF_RND(6)   x0 += k1; x1 += kx + 1u;
    TF_RND(17) TF_RND(29) TF_RND(16) TF_RND(24)  x0 += kx; x1 += k0 + 2u;
    TF_RND(13) TF_RND(15) TF_RND(26) TF_RND(6)   x0 += k0; x1 += k1 + 3u;
    TF_RND(17) TF_RND(29) TF_RND(16) TF_RND(24)  x0 += k1; x1 += kx + 4u;
    TF_RND(13) TF_RND(15) TF_RND(26) TF_RND(6)   x0 += kx; x1 += k0 + 5u;
#undef TF_RND
    y0 = x0; y1 = x1;
}

// PARTITIONABLE random_bits (32-bit): for flat 64-bit index i (< 2^32 here),
// bits[i] = y0(0, i) XOR y1(0, i).
__device__ __forceinline__ uint32_t gamma_bits(uint32_t k0, uint32_t k1,
                                               uint32_t idx) {
    uint32_t y0, y1;
    tf2x32(k0, k1, 0u, idx, y0, y1);
    return y0 ^ y1;
}

__device__ __forceinline__ float bits_to_u01(uint32_t bits) {
    return __uint_as_float((bits >> 9) | 0x3F800000u) - 1.0f;
}

// XLA ErfInv32 (Giles). Plain mul/add (no fma) to match XLA's emission.
__device__ __forceinline__ float erfinv_xla(float x) {
    float w = -log1pf(-__fmul_rn(x, x));
    float p;
    if (w < 5.0f) {
        w = __fadd_rn(w, -2.5f);
        p = 2.81022636e-08f;
        p = __fadd_rn(__fmul_rn(p, w),  3.43273939e-07f);
        p = __fadd_rn(__fmul_rn(p, w), -3.5233877e-06f);
        p = __fadd_rn(__fmul_rn(p, w), -4.39150654e-06f);
        p = __fadd_rn(__fmul_rn(p, w),  0.00021858087f);
        p = __fadd_rn(__fmul_rn(p, w), -0.00125372503f);
        p = __fadd_rn(__fmul_rn(p, w), -0.00417768164f);
        p = __fadd_rn(__fmul_rn(p, w),  0.246640727f);
        p = __fadd_rn(__fmul_rn(p, w),  1.50140941f);
    } else {
        w = __fadd_rn(__fsqrt_rn(w), -3.0f);
        p = -0.000200214257f;
        p = __fadd_rn(__fmul_rn(p, w),  0.000100950558f);
        p = __fadd_rn(__fmul_rn(p, w),  0.00134934322f);
        p = __fadd_rn(__fmul_rn(p, w), -0.00367342844f);
        p = __fadd_rn(__fmul_rn(p, w),  0.00573950773f);
        p = __fadd_rn(__fmul_rn(p, w), -0.0076224613f);
        p = __fadd_rn(__fmul_rn(p, w),  0.00943887047f);
        p = __fadd_rn(__fmul_rn(p, w),  1.00167406f);
        p = __fadd_rn(__fmul_rn(p, w),  2.83297682f);
    }
    return __fmul_rn(p, x);
}

// jax.nn.softplus = logaddexp(x, 0) = max(x,0) + log1p(exp(-|x|))
__device__ __forceinline__ float softplusf(float x) {
    return __fadd_rn(fmaxf(x, 0.0f), log1pf(expf(-fabsf(x))));
}

// ---------------------------------------------------------------------------
// Generic fp32 GEMM:  C[M,N] = act(A[M,K] @ B[K,N] + bias[N])
// ---------------------------------------------------------------------------
template <int BM, int BN, int BK, int TM, int TN, int ACT>
__global__ __launch_bounds__((BM / TM) * (BN / TN))
void sgemm_bias(const float* __restrict__ A, const float* __restrict__ Bm,
                const float* __restrict__ bias, float* __restrict__ C,
                int M, int N, int K) {
    constexpr int NT = (BM / TM) * (BN / TN);
    __shared__ float As[BK][BM];
    __shared__ float Bs[BK][BN];

    const int tid  = threadIdx.x;
    const int row0 = blockIdx.y * BM;
    const int col0 = blockIdx.x * BN;
    const int tr   = tid / (BN / TN);
    const int tc   = tid % (BN / TN);

    float acc[TM][TN] = {};

    constexpr int A_ITERS = (BM * BK) / (NT * 4);
    constexpr int B_ITERS = (BK * BN) / (NT * 4);

    for (int k0 = 0; k0 < K; k0 += BK) {
#pragma unroll
        for (int it = 0; it < A_ITERS; ++it) {
            int off = tid * 4 + it * NT * 4;
            int r = off / BK, c = off % BK;
            float4 v = *reinterpret_cast<const float4*>(
                &A[(size_t)(row0 + r) * K + k0 + c]);
            As[c + 0][r] = v.x; As[c + 1][r] = v.y;
            As[c + 2][r] = v.z; As[c + 3][r] = v.w;
        }
#pragma unroll
        for (int it = 0; it < B_ITERS; ++it) {
            int off = tid * 4 + it * NT * 4;
            int r = off / BN, c = off % BN;
            *reinterpret_cast<float4*>(&Bs[r][c]) =
                *reinterpret_cast<const float4*>(&Bm[(size_t)(k0 + r) * N + col0 + c]);
        }
        __syncthreads();
#pragma unroll
        for (int kk = 0; kk < BK; ++kk) {
            float regM[TM], regN[TN];
#pragma unroll
            for (int i = 0; i < TM; i += 4)
                *reinterpret_cast<float4*>(&regM[i]) =
                    *reinterpret_cast<const float4*>(&As[kk][tr * TM + i]);
#pragma unroll
            for (int j = 0; j < TN; j += 4)
                *reinterpret_cast<float4*>(&regN[j]) =
                    *reinterpret_cast<const float4*>(&Bs[kk][tc * TN + j]);
#pragma unroll
            for (int i = 0; i < TM; ++i)
#pragma unroll
                for (int j = 0; j < TN; ++j)
                    acc[i][j] = fmaf(regM[i], regN[j], acc[i][j]);
        }
        __syncthreads();
    }

#pragma unroll
    for (int i = 0; i < TM; ++i) {
        int r = row0 + tr * TM + i;
#pragma unroll
        for (int j = 0; j < TN; j += 4) {
            int c = col0 + tc * TN + j;
            float4 v;
            v.x = acc[i][j + 0] + bias[c + 0];
            v.y = acc[i][j + 1] + bias[c + 1];
            v.z = acc[i][j + 2] + bias[c + 2];
            v.w = acc[i][j + 3] + bias[c + 3];
            if (ACT == 1) {
                v.x = fmaxf(v.x, 0.0f); v.y = fmaxf(v.y, 0.0f);
                v.z = fmaxf(v.z, 0.0f); v.w = fmaxf(v.w, 0.0f);
            }
            *reinterpret_cast<float4*>(&C[(size_t)r * N + c]) = v;
        }
    }
}

// ---------------------------------------------------------------------------
// Gamma sampler: softplus heads + Marsaglia-Tsang rejection (JAX RNG exact)
// ---------------------------------------------------------------------------
__global__ __launch_bounds__(256)
void gamma_sampler(const float* __restrict__ preA, const float* __restrict__ preB,
                   float* __restrict__ out_la, float* __restrict__ out_lb,
                   float* __restrict__ out_z,  float* __restrict__ z_buf) {
    int i = blockIdx.x * blockDim.x + threadIdx.x;
    if (i >= BATCHN * LATENT) return;

    float al = __fadd_rn(1e-6f, softplusf(preA[i]));
    float be = __fadd_rn(1e-6f, softplusf(preB[i]));

    float d  = __fadd_rn(__fadd_rn(al, 1.0f), -(1.0f / 3.0f));
    float cc = __fdiv_rn(1.0f, __fsqrt_rn(__fmul_rn(9.0f, d)));

    const float LO     = -0.99999994f;        // nextafter(-1, 0) in f32
    const float SPAN_N = 2.0f;                // f32(1.0 - LO)
    const float UMIN   = 1e-7f;
    const float SPAN_U = 1.0f - 1e-7f;        // f32 rounding at compile time
    const float SQRT2  = 1.41421356f;

    float eps_s = 0.0f, u_s = 0.0f, eps0 = 0.0f, u0 = 0.0f;
    bool found = false;

#pragma unroll 1
    for (int k = 0; k < KROUNDS; ++k) {
        uint32_t idx = (uint32_t)k * GAMMA_N + (uint32_t)i;
        uint32_t bn = gamma_bits(KEY_N0, KEY_N1, idx);
        uint32_t bu = gamma_bits(KEY_U0, KEY_U1, idx);

        float un = __fadd_rn(__fmul_rn(bits_to_u01(bn), SPAN_N), LO);
        un = fmaxf(LO, un);
        float eps = __fmul_rn(SQRT2, erfinv_xla(un));

        float uu = __fadd_rn(__fmul_rn(bits_to_u01(bu), SPAN_U), UMIN);
        uu = fmaxf(UMIN, uu);

        if (k == 0) { eps0 = eps; u0 = uu; }

        float v = __fadd_rn(1.0f, __fmul_rn(cc, eps));
        bool acc = false;
        if (v > 0.0f) {
            float e2 = __fmul_rn(eps, eps);
            float squeeze = __fadd_rn(1.0f,
                -__fmul_rn(__fmul_rn(0.0331f, e2), e2));
            if (uu < squeeze) {
                acc = true;
            } else {
                float v3  = __fmul_rn(__fmul_rn(v, v), v);
                float inner = __fadd_rn(__fadd_rn(1.0f, -v3), logf(v3));
                float rhs = __fadd_rn(__fmul_rn(__fmul_rn(0.5f, eps), eps),
                                      __fmul_rn(d, inner));
                if (logf(uu) < rhs) acc = true;
            }
        }
        if (acc) { eps_s = eps; u_s = uu; found = true; break; }
    }
    if (!found) { eps_s = eps0; u_s = u0; }   // argmax of all-False == 0

    float v1 = __fadd_rn(1.0f, __fmul_rn(cc, eps_s));
    float vs = __fmul_rn(v1, __fmul_rn(v1, v1));
    float t1 = logf(__fadd_rn(__fmul_rn(d, vs), 1e-6f));
    float t2 = __fdiv_rn(logf(__fadd_rn(u_s, 1e-6f)), __fadd_rn(al, 1e-6f));
    float z  = __fdiv_rn(expf(__fadd_rn(t1, t2)), __fadd_rn(be, 1e-6f));

    out_la[i] = al;
    out_lb[i] = be;
    out_z[i]  = z;
    z_buf[i]  = z;
}

// ---------------------------------------------------------------------------
// Final epilogue: recon_al/recon_be = 1e-6 + softplus(dec[:, :2048 / 2048:])
// ---------------------------------------------------------------------------
__global__ __launch_bounds__(256)
void dec_split_softplus(const float* __restrict__ dec,
                        float* __restrict__ oa, float* __restrict__ ob) {
    int t = blockIdx.x * blockDim.x + threadIdx.x;
    if (t >= 8192 * 512) return;
    int r  = t >> 9;
    int c4 = (t & 511) << 2;
    const float4 a = *reinterpret_cast<const float4*>(&dec[(size_t)r * 4096 + c4]);
    const float4 b = *reinterpret_cast<const float4*>(&dec[(size_t)r * 4096 + 2048 + c4]);
    float4 ra, rb;
    ra.x = __fadd_rn(1e-6f, softplusf(a.x));
    ra.y = __fadd_rn(1e-6f, softplusf(a.y));
    ra.z = __fadd_rn(1e-6f, softplusf(a.z));
    ra.w = __fadd_rn(1e-6f, softplusf(a.w));
    rb.x = __fadd_rn(1e-6f, softplusf(b.x));
    rb.y = __fadd_rn(1e-6f, softplusf(b.y));
    rb.z = __fadd_rn(1e-6f, softplusf(b.z));
    rb.w = __fadd_rn(1e-6f, softplusf(b.w));
    *reinterpret_cast<float4*>(&oa[(size_t)r * 2048 + c4]) = ra;
    *reinterpret_cast<float4*>(&ob[(size_t)r * 2048 + c4]) = rb;
}

// ---------------------------------------------------------------------------
// Launch
// ---------------------------------------------------------------------------
extern "C" void kernel_launch(void* const* d_in, const int* in_sizes, int n_in,
                              void* d_out, int out_size) {
    (void)in_sizes; (void)n_in; (void)out_size;

    const float* x    = (const float*)d_in[0];
    const float* f1w  = (const float*)d_in[1];
    const float* f1b  = (const float*)d_in[2];
    const float* f2w  = (const float*)d_in[3];
    const float* f2b  = (const float*)d_in[4];
    const float* f3w  = (const float*)d_in[5];
    const float* f3b  = (const float*)d_in[6];
    const float* f41w = (const float*)d_in[7];
    const float* f41b = (const float*)d_in[8];
    const float* f42w = (const float*)d_in[9];
    const float* f42b = (const float*)d_in[10];
    const float* f4w  = (const float*)d_in[11];
    const float* f4b  = (const float*)d_in[12];
    const float* f5w  = (const float*)d_in[13];
    const float* f5b  = (const float*)d_in[14];
    const float* f6w  = (const float*)d_in[15];
    const float* f6b  = (const float*)d_in[16];
    const float* f7w  = (const float*)d_in[17];
    const float* f7b  = (const float*)d_in[18];

    float* out = (float*)d_out;
    const size_t OFF_BE = 8192ull * 2048;
    const size_t OFF_LA = 2 * OFF_BE;
    const size_t OFF_LB = OFF_LA + 524288;
    const size_t OFF_Z  = OFF_LB + 524288;

    float *b0, *b1, *dec, *pA, *pB, *z;
    cudaGetSymbolAddress((void**)&b0,  g_buf0);
    cudaGetSymbolAddress((void**)&b1,  g_buf1);
    cudaGetSymbolAddress((void**)&dec, g_dec);
    cudaGetSymbolAddress((void**)&pA,  g_preA);
    cudaGetSymbolAddress((void**)&pB,  g_preB);
    cudaGetSymbolAddress((void**)&z,   g_z);

    // encoder
    sgemm_bias<128, 128, 8, 8, 8, 1><<<dim3(1024 / 128, 8192 / 128), 256>>>(
        x, f1w, f1b, b0, 8192, 1024, 2048);
    sgemm_bias<128, 128, 8, 8, 8, 1><<<dim3(1024 / 128, 8192 / 128), 256>>>(
        b0, f2w, f2b, b1, 8192, 1024, 1024);
    sgemm_bias<128, 128, 8, 8, 8, 1><<<dim3(2048 / 128, 8192 / 128), 256>>>(
        b1, f3w, f3b, b0, 8192, 2048, 1024);
    // heads (N=64)
    sgemm_bias<64, 64, 16, 4, 4, 0><<<dim3(1, 8192 / 64), 256>>>(
        b0, f41w, f41b, pA, 8192, 64, 2048);
    sgemm_bias<64, 64, 16, 4, 4, 0><<<dim3(1, 8192 / 64), 256>>>(
        b0, f42w, f42b, pB, 8192, 64, 2048);
    // gamma reparameterization
    gamma_sampler<<<(BATCHN * LATENT) / 256, 256>>>(
        pA, pB, out + OFF_LA, out + OFF_LB, out + OFF_Z, z);
    // decoder
    sgemm_bias<128, 128, 8, 8, 8, 1><<<dim3(2048 / 128, 8192 / 128), 256>>>(
        z, f4w, f4b, b1, 8192, 2048, 64);
    sgemm_bias<128, 128, 8, 8, 8, 1><<<dim3(1024 / 128, 8192 / 128), 256>>>(
        b1, f5w, f5b, b0, 8192, 1024, 2048);
    sgemm_bias<128, 128, 8, 8, 8, 1><<<dim3(1024 / 128, 8192 / 128), 256>>>(
        b0, f6w, f6b, b1, 8192, 1024, 1024);
    sgemm_bias<128, 128, 8, 8, 8, 0><<<dim3(4096 / 128, 8192 / 128), 256>>>(
        b1, f7w, f7b, dec, 8192, 4096, 1024);
    // split softplus outputs
    dec_split_softplus<<<(8192 * 512) / 256, 256>>>(dec, out, out + OFF_BE);
}

// round 4
// speedup vs baseline: 1.5997x; 1.5997x over previous
#include <cuda_runtime.h>
#include <cstdint>
#include <cstddef>

// ============================================================================
// VAE_gamma on GB300 via mma.sync (tf32 3x split = fp32-accurate GEMMs),
// fused epilogues, JAX partitionable-threefry gamma sampler.
// tcgen05 is unavailable (harness compiles compute_103 PTX, no 'a' features),
// so we use arch-generic mma.sync.m16n8k8.tf32 (HMMA path on sm_103a).
// ============================================================================

#define BATCHN   8192
#define LATENT   64
#define KROUNDS  24
#define GAMMA_N  524288u

// ---------------------------------------------------------------------------
// Scratch
// ---------------------------------------------------------------------------
__device__ float g_buf0[8192 * 2048];
__device__ float g_buf1[8192 * 2048];
__device__ float g_pre [8192 * 128];
__device__ float g_z   [8192 * 64];
__device__ float g_wt  [12976128];      // all transposed weights [N][K] fp32
__device__ float g_bh  [128];           // concat head bias

#define OW1  0u                         // [1024][2048]
#define OW2  (OW1 + 2097152u)           // [1024][1024]
#define OW3  (OW2 + 1048576u)           // [2048][1024]
#define OWH  (OW3 + 2097152u)           // [128][2048]
#define OW4  (OWH + 262144u)            // [2048][64]
#define OW5  (OW4 + 131072u)            // [1024][2048]
#define OW6  (OW5 + 2097152u)           // [1024][1024]
#define OW7  (OW6 + 1048576u)           // [4096][1024]

// ---------------------------------------------------------------------------
// Threefry-2x32 (JAX partitionable mode)
// ---------------------------------------------------------------------------
constexpr unsigned rotlc(unsigned x, int r) { return (x << r) | (x >> (32 - r)); }
constexpr unsigned long long tf_const(unsigned k0, unsigned k1,
                                      unsigned x0, unsigned x1) {
    unsigned kx = k0 ^ k1 ^ 0x1BD11BDAu;
    unsigned ks[3] = {k0, k1, kx};
    const int R0[4] = {13, 15, 26, 6};
    const int R1[4] = {17, 29, 16, 24};
    x0 += k0; x1 += k1;
    for (int i = 0; i < 5; i++) {
        const int* rr = (i % 2 == 0) ? R0 : R1;
        for (int j = 0; j < 4; j++) { x0 += x1; x1 = rotlc(x1, rr[j]); x1 ^= x0; }
        x0 += ks[(i + 1) % 3];
        x1 += ks[(i + 2) % 3] + (unsigned)(i + 1);
    }
    return ((unsigned long long)x0 << 32) | x1;
}
constexpr unsigned long long SPN = tf_const(0u, 42u, 0u, 0u);
constexpr unsigned long long SPU = tf_const(0u, 42u, 0u, 1u);
constexpr unsigned KEY_N0 = (unsigned)(SPN >> 32);
constexpr unsigned KEY_N1 = (unsigned)(SPN & 0xFFFFFFFFu);
constexpr unsigned KEY_U0 = (unsigned)(SPU >> 32);
constexpr unsigned KEY_U1 = (unsigned)(SPU & 0xFFFFFFFFu);

__device__ __forceinline__ uint32_t rotl32(uint32_t x, int r) {
    return __funnelshift_l(x, x, r);
}
__device__ __forceinline__ void tf2x32(uint32_t k0, uint32_t k1,
                                       uint32_t x0, uint32_t x1,
                                       uint32_t& y0, uint32_t& y1) {
    uint32_t kx = k0 ^ k1 ^ 0x1BD11BDAu;
    x0 += k0; x1 += k1;
#define TF_RND(r) { x0 += x1; x1 = rotl32(x1, r); x1 ^= x0; }
    TF_RND(13) TF_RND(15) TF_RND(26) TF_RND(6)   x0 += k1; x1 += kx + 1u;
    TF_RND(17) TF_RND(29) TF_RND(16) TF_RND(24)  x0 += kx; x1 += k0 + 2u;
    TF_RND(13) TF_RND(15) TF_RND(26) TF_RND(6)   x0 += k0; x1 += k1 + 3u;
    TF_RND(17) TF_RND(29) TF_RND(16) TF_RND(24)  x0 += k1; x1 += kx + 4u;
    TF_RND(13) TF_RND(15) TF_RND(26) TF_RND(6)   x0 += kx; x1 += k0 + 5u;
#undef TF_RND
    y0 = x0; y1 = x1;
}
__device__ __forceinline__ uint32_t gamma_bits(uint32_t k0, uint32_t k1,
                                               uint32_t idx) {
    uint32_t y0, y1;
    tf2x32(k0, k1, 0u, idx, y0, y1);
    return y0 ^ y1;
}
__device__ __forceinline__ float bits_to_u01(uint32_t bits) {
    return __uint_as_float((bits >> 9) | 0x3F800000u) - 1.0f;
}
__device__ __forceinline__ float erfinv_xla(float x) {
    float w = -log1pf(-__fmul_rn(x, x));
    float p;
    if (w < 5.0f) {
        w = __fadd_rn(w, -2.5f);
        p = 2.81022636e-08f;
        p = __fadd_rn(__fmul_rn(p, w),  3.43273939e-07f);
        p = __fadd_rn(__fmul_rn(p, w), -3.5233877e-06f);
        p = __fadd_rn(__fmul_rn(p, w), -4.39150654e-06f);
        p = __fadd_rn(__fmul_rn(p, w),  0.00021858087f);
        p = __fadd_rn(__fmul_rn(p, w), -0.00125372503f);
        p = __fadd_rn(__fmul_rn(p, w), -0.00417768164f);
        p = __fadd_rn(__fmul_rn(p, w),  0.246640727f);
        p = __fadd_rn(__fmul_rn(p, w),  1.50140941f);
    } else {
        w = __fadd_rn(__fsqrt_rn(w), -3.0f);
        p = -0.000200214257f;
        p = __fadd_rn(__fmul_rn(p, w),  0.000100950558f);
        p = __fadd_rn(__fmul_rn(p, w),  0.00134934322f);
        p = __fadd_rn(__fmul_rn(p, w), -0.00367342844f);
        p = __fadd_rn(__fmul_rn(p, w),  0.00573950773f);
        p = __fadd_rn(__fmul_rn(p, w), -0.0076224613f);
        p = __fadd_rn(__fmul_rn(p, w),  0.00943887047f);
        p = __fadd_rn(__fmul_rn(p, w),  1.00167406f);
        p = __fadd_rn(__fmul_rn(p, w),  2.83297682f);
    }
    return __fmul_rn(p, x);
}
__device__ __forceinline__ float softplusf(float x) {
    return __fadd_rn(fmaxf(x, 0.0f), log1pf(expf(-fabsf(x))));
}

// ---------------------------------------------------------------------------
// tf32 helpers
// ---------------------------------------------------------------------------
__device__ __forceinline__ float tf32_hi(float x) {
    return __uint_as_float(__float_as_uint(x) & 0xFFFFE000u);
}
__device__ __forceinline__ void mma_tf32(float* c, const float* a, const float* b) {
    asm volatile(
        "mma.sync.aligned.m16n8k8.row.col.f32.tf32.tf32.f32 "
        "{%0,%1,%2,%3}, {%4,%5,%6,%7}, {%8,%9}, {%0,%1,%2,%3};"
        : "+f"(c[0]), "+f"(c[1]), "+f"(c[2]), "+f"(c[3])
        : "r"(__float_as_uint(a[0])), "r"(__float_as_uint(a[1])),
          "r"(__float_as_uint(a[2])), "r"(__float_as_uint(a[3])),
          "r"(__float_as_uint(b[0])), "r"(__float_as_uint(b[1])));
}

// ---------------------------------------------------------------------------
// mma.sync tf32x3 GEMM: C[M,N] = act(A[M,K] @ Bt[N,K]^T + bias)
//   CTA tile 128x128, BK=32, 256 threads = 8 warps (2m x 4n), warp tile 64x32.
//   ACT: 0 none, 1 relu, 2 softplus-split (fc7).
// ---------------------------------------------------------------------------
#define LDSK 36                         // padded k-stride (conflict-free)
#define PLANE (128 * LDSK)              // floats per plane
#define STAGEF (4 * PLANE)              // A_hi A_lo B_hi B_lo

template <int ACT>
__global__ __launch_bounds__(256)
void mma_gemm(const float* __restrict__ A, const float* __restrict__ Bt,
              const float* __restrict__ bias, float* __restrict__ C,
              float* __restrict__ C2, int K, int ldc) {
    extern __shared__ float sm[];
    __shared__ float s_bias[128];

    const int tid  = threadIdx.x;
    const int wid  = tid >> 5;
    const int lane = tid & 31;
    const int qr   = lane >> 2;         // 0..7
    const int qc   = lane & 3;          // 0..3
    const int m_w  = (wid >> 2) * 64;   // warp m offset
    const int n_w  = (wid & 3) * 32;    // warp n offset
    const int row0 = blockIdx.y * 128;
    const int col0 = blockIdx.x * 128;

    if (tid < 128) s_bias[tid] = bias[col0 + tid];

    float acc[4][4][4];
#pragma unroll
    for (int a = 0; a < 4; ++a)
#pragma unroll
        for (int b = 0; b < 4; ++b)
#pragma unroll
            for (int c = 0; c < 4; ++c) acc[a][b][c] = 0.0f;

    const int NCH = K >> 5;
    float4 av[4], bv[4];

    // ---- prolog: load + convert/store chunk 0 ----
#pragma unroll
    for (int j = 0; j < 4; ++j) {
        int idx = j * 256 + tid;
        int r = idx >> 3, kq = (idx & 7) << 2;
        av[j] = *reinterpret_cast<const float4*>(&A [(size_t)(row0 + r) * K + kq]);
        bv[j] = *reinterpret_cast<const float4*>(&Bt[(size_t)(col0 + r) * K + kq]);
    }
    {
        float* Sa_h = sm;
        float* Sa_l = Sa_h + PLANE;
        float* Sb_h = Sa_h + 2 * PLANE;
        float* Sb_l = Sa_h + 3 * PLANE;
#pragma unroll
        for (int j = 0; j < 4; ++j) {
            int idx = j * 256 + tid;
            int r = idx >> 3, kq = (idx & 7) << 2;
            int off = r * LDSK + kq;
            float4 hi, lo;
            hi.x = tf32_hi(av[j].x); lo.x = __fadd_rn(av[j].x, -hi.x);
            hi.y = tf32_hi(av[j].y); lo.y = __fadd_rn(av[j].y, -hi.y);
            hi.z = tf32_hi(av[j].z); lo.z = __fadd_rn(av[j].z, -hi.z);
            hi.w = tf32_hi(av[j].w); lo.w = __fadd_rn(av[j].w, -hi.w);
            *reinterpret_cast<float4*>(&Sa_h[off]) = hi;
            *reinterpret_cast<float4*>(&Sa_l[off]) = lo;
            hi.x = tf32_hi(bv[j].x); lo.x = __fadd_rn(bv[j].x, -hi.x);
            hi.y = tf32_hi(bv[j].y); lo.y = __fadd_rn(bv[j].y, -hi.y);
            hi.z = tf32_hi(bv[j].z); lo.z = __fadd_rn(bv[j].z, -hi.z);
            hi.w = tf32_hi(bv[j].w); lo.w = __fadd_rn(bv[j].w, -hi.w);
            *reinterpret_cast<float4*>(&Sb_h[off]) = hi;
            *reinterpret_cast<float4*>(&Sb_l[off]) = lo;
        }
    }
    __syncthreads();

    for (int i = 0; i < NCH; ++i) {
        // prefetch next chunk into registers
        if (i + 1 < NCH) {
            int k0 = (i + 1) << 5;
#pragma unroll
            for (int j = 0; j < 4; ++j) {
                int idx = j * 256 + tid;
                int r = idx >> 3, kq = (idx & 7) << 2;
                av[j] = *reinterpret_cast<const float4*>(&A [(size_t)(row0 + r) * K + k0 + kq]);
                bv[j] = *reinterpret_cast<const float4*>(&Bt[(size_t)(col0 + r) * K + k0 + kq]);
            }
        }

        // compute on stage i&1
        {
            const float* Sa_h = sm + (i & 1) * STAGEF;
            const float* Sa_l = Sa_h + PLANE;
            const float* Sb_h = Sa_h + 2 * PLANE;
            const float* Sb_l = Sa_h + 3 * PLANE;
#pragma unroll
            for (int ks = 0; ks < 4; ++ks) {
                int kk = (ks << 3) + qc;
                float ah[4][4], al[4][4];
#pragma unroll
                for (int mt = 0; mt < 4; ++mt) {
                    int ro = (m_w + mt * 16 + qr) * LDSK;
                    ah[mt][0] = Sa_h[ro + kk];
                    ah[mt][1] = Sa_h[ro + 8 * LDSK + kk];
                    ah[mt][2] = Sa_h[ro + kk + 4];
                    ah[mt][3] = Sa_h[ro + 8 * LDSK + kk + 4];
                    al[mt][0] = Sa_l[ro + kk];
                    al[mt][1] = Sa_l[ro + 8 * LDSK + kk];
                    al[mt][2] = Sa_l[ro + kk + 4];
                    al[mt][3] = Sa_l[ro + 8 * LDSK + kk + 4];
                }
                float bh[4][2], bl[4][2];
#pragma unroll
                for (int nt = 0; nt < 4; ++nt) {
                    int co = (n_w + nt * 8 + qr) * LDSK + (ks << 3) + qc;
                    bh[nt][0] = Sb_h[co];
                    bh[nt][1] = Sb_h[co + 4];
                    bl[nt][0] = Sb_l[co];
                    bl[nt][1] = Sb_l[co + 4];
                }
#pragma unroll
                for (int mt = 0; mt < 4; ++mt)
#pragma unroll
                    for (int nt = 0; nt < 4; ++nt) {
                        mma_tf32(acc[mt][nt], ah[mt], bh[nt]);
                        mma_tf32(acc[mt][nt], ah[mt], bl[nt]);
                        mma_tf32(acc[mt][nt], al[mt], bh[nt]);
                    }
            }
        }

        // store next chunk into the other stage
        if (i + 1 < NCH) {
            float* Sa_h = sm + ((i + 1) & 1) * STAGEF;
            float* Sa_l = Sa_h + PLANE;
            float* Sb_h = Sa_h + 2 * PLANE;
            float* Sb_l = Sa_h + 3 * PLANE;
#pragma unroll
            for (int j = 0; j < 4; ++j) {
                int idx = j * 256 + tid;
                int r = idx >> 3, kq = (idx & 7) << 2;
                int off = r * LDSK + kq;
                float4 hi, lo;
                hi.x = tf32_hi(av[j].x); lo.x = __fadd_rn(av[j].x, -hi.x);
                hi.y = tf32_hi(av[j].y); lo.y = __fadd_rn(av[j].y, -hi.y);
                hi.z = tf32_hi(av[j].z); lo.z = __fadd_rn(av[j].z, -hi.z);
                hi.w = tf32_hi(av[j].w); lo.w = __fadd_rn(av[j].w, -hi.w);
                *reinterpret_cast<float4*>(&Sa_h[off]) = hi;
                *reinterpret_cast<float4*>(&Sa_l[off]) = lo;
                hi.x = tf32_hi(bv[j].x); lo.x = __fadd_rn(bv[j].x, -hi.x);
                hi.y = tf32_hi(bv[j].y); lo.y = __fadd_rn(bv[j].y, -hi.y);
                hi.z = tf32_hi(bv[j].z); lo.z = __fadd_rn(bv[j].z, -hi.z);
                hi.w = tf32_hi(bv[j].w); lo.w = __fadd_rn(bv[j].w, -hi.w);
                *reinterpret_cast<float4*>(&Sb_h[off]) = hi;
                *reinterpret_cast<float4*>(&Sb_l[off]) = lo;
            }
            __syncthreads();
        }
    }

    // ---- epilogue: bias + activation, direct float2 stores ----
#pragma unroll
    for (int mt = 0; mt < 4; ++mt) {
        int r = row0 + m_w + mt * 16 + qr;
#pragma unroll
        for (int nt = 0; nt < 4; ++nt) {
            int lc = n_w + nt * 8 + 2 * qc;
            int gc = col0 + lc;
            float2 t0, t1;
            t0.x = acc[mt][nt][0] + s_bias[lc];
            t0.y = acc[mt][nt][1] + s_bias[lc + 1];
            t1.x = acc[mt][nt][2] + s_bias[lc];
            t1.y = acc[mt][nt][3] + s_bias[lc + 1];
            if (ACT == 1) {
                t0.x = fmaxf(t0.x, 0.0f); t0.y = fmaxf(t0.y, 0.0f);
                t1.x = fmaxf(t1.x, 0.0f); t1.y = fmaxf(t1.y, 0.0f);
            }
            if (ACT == 2) {
                t0.x = __fadd_rn(1e-6f, softplusf(t0.x));
                t0.y = __fadd_rn(1e-6f, softplusf(t0.y));
                t1.x = __fadd_rn(1e-6f, softplusf(t1.x));
                t1.y = __fadd_rn(1e-6f, softplusf(t1.y));
            }
            if (ACT == 2) {
                if (gc < 2048) {
                    *reinterpret_cast<float2*>(&C [(size_t)r * 2048 + gc]) = t0;
                    *reinterpret_cast<float2*>(&C [(size_t)(r + 8) * 2048 + gc]) = t1;
                } else {
                    *reinterpret_cast<float2*>(&C2[(size_t)r * 2048 + gc - 2048]) = t0;
                    *reinterpret_cast<float2*>(&C2[(size_t)(r + 8) * 2048 + gc - 2048]) = t1;
                }
            } else {
                *reinterpret_cast<float2*>(&C[(size_t)r * ldc + gc]) = t0;
                *reinterpret_cast<float2*>(&C[(size_t)(r + 8) * ldc + gc]) = t1;
            }
        }
    }
}

// ---------------------------------------------------------------------------
// Weight transpose prep: W[K,N] fp32 -> Wt[N,K] fp32
// ---------------------------------------------------------------------------
__global__ __launch_bounds__(256)
void transpose_w(const float* __restrict__ W, float* __restrict__ Wt,
                 int K, int N) {
    __shared__ float s[32][33];
    int n0 = blockIdx.x * 32, k0 = blockIdx.y * 32;
    int t = threadIdx.x;
    int a = t >> 5, b = t & 31;
#pragma unroll
    for (int p = 0; p < 4; ++p) {
        int k = p * 8 + a;
        s[k][b] = W[(size_t)(k0 + k) * N + n0 + b];
    }
    __syncthreads();
#pragma unroll
    for (int p = 0; p < 4; ++p) {
        int n = p * 8 + a;
        Wt[(size_t)(n0 + n) * K + k0 + b] = s[b][n];
    }
}

__global__ void concat_head_bias(const float* b1, const float* b2, float* o) {
    int t = threadIdx.x;
    o[t] = (t < 64) ? b1[t] : b2[t - 64];
}

// ---------------------------------------------------------------------------
// Gamma sampler (reads fused head buffer g_pre[row][0:64 | 64:128])
// ---------------------------------------------------------------------------
__global__ __launch_bounds__(256)
void gamma_sampler(const float* __restrict__ pre,
                   float* __restrict__ out_la, float* __restrict__ out_lb,
                   float* __restrict__ out_z,  float* __restrict__ z_buf) {
    int i = blockIdx.x * blockDim.x + threadIdx.x;
    if (i >= BATCHN * LATENT) return;
    int row = i >> 6, lat = i & 63;

    float al = __fadd_rn(1e-6f, softplusf(pre[row * 128 + lat]));
    float be = __fadd_rn(1e-6f, softplusf(pre[row * 128 + 64 + lat]));

    float d  = __fadd_rn(__fadd_rn(al, 1.0f), -(1.0f / 3.0f));
    float cc = __fdiv_rn(1.0f, __fsqrt_rn(__fmul_rn(9.0f, d)));

    const float LO     = -0.99999994f;
    const float SPAN_N = 2.0f;
    const float UMIN   = 1e-7f;
    const float SPAN_U = 1.0f - 1e-7f;
    const float SQRT2  = 1.41421356f;

    float eps_s = 0.0f, u_s = 0.0f, eps0 = 0.0f, u0 = 0.0f;
    bool found = false;

#pragma unroll 1
    for (int k = 0; k < KROUNDS; ++k) {
        uint32_t idx = (uint32_t)k * GAMMA_N + (uint32_t)i;
        uint32_t bn = gamma_bits(KEY_N0, KEY_N1, idx);
        uint32_t bu = gamma_bits(KEY_U0, KEY_U1, idx);

        float un = __fadd_rn(__fmul_rn(bits_to_u01(bn), SPAN_N), LO);
        un = fmaxf(LO, un);
        float eps = __fmul_rn(SQRT2, erfinv_xla(un));

        float uu = __fadd_rn(__fmul_rn(bits_to_u01(bu), SPAN_U), UMIN);
        uu = fmaxf(UMIN, uu);

        if (k == 0) { eps0 = eps; u0 = uu; }

        float v = __fadd_rn(1.0f, __fmul_rn(cc, eps));
        bool acc = false;
        if (v > 0.0f) {
            float e2 = __fmul_rn(eps, eps);
            float squeeze = __fadd_rn(1.0f, -__fmul_rn(__fmul_rn(0.0331f, e2), e2));
            if (uu < squeeze) {
                acc = true;
            } else {
                float v3 = __fmul_rn(__fmul_rn(v, v), v);
                float inner = __fadd_rn(__fadd_rn(1.0f, -v3), logf(v3));
                float rhs = __fadd_rn(__fmul_rn(__fmul_rn(0.5f, eps), eps),
                                      __fmul_rn(d, inner));
                if (logf(uu) < rhs) acc = true;
            }
        }
        if (acc) { eps_s = eps; u_s = uu; found = true; break; }
    }
    if (!found) { eps_s = eps0; u_s = u0; }

    float v1 = __fadd_rn(1.0f, __fmul_rn(cc, eps_s));
    float vs = __fmul_rn(v1, __fmul_rn(v1, v1));
    float t1 = logf(__fadd_rn(__fmul_rn(d, vs), 1e-6f));
    float t2 = __fdiv_rn(logf(__fadd_rn(u_s, 1e-6f)), __fadd_rn(al, 1e-6f));
    float z  = __fdiv_rn(expf(__fadd_rn(t1, t2)), __fadd_rn(be, 1e-6f));

    out_la[i] = al;
    out_lb[i] = be;
    out_z[i]  = z;
    z_buf[i]  = z;
}

// ---------------------------------------------------------------------------
// Launch
// ---------------------------------------------------------------------------
extern "C" void kernel_launch(void* const* d_in, const int* in_sizes, int n_in,
                              void* d_out, int out_size) {
    (void)in_sizes; (void)n_in; (void)out_size;

    const float* x    = (const float*)d_in[0];
    const float* f1w  = (const float*)d_in[1];
    const float* f1b  = (const float*)d_in[2];
    const float* f2w  = (const float*)d_in[3];
    const float* f2b  = (const float*)d_in[4];
    const float* f3w  = (const float*)d_in[5];
    const float* f3b  = (const float*)d_in[6];
    const float* f41w = (const float*)d_in[7];
    const float* f41b = (const float*)d_in[8];
    const float* f42w = (const float*)d_in[9];
    const float* f42b = (const float*)d_in[10];
    const float* f4w  = (const float*)d_in[11];
    const float* f4b  = (const float*)d_in[12];
    const float* f5w  = (const float*)d_in[13];
    const float* f5b  = (const float*)d_in[14];
    const float* f6w  = (const float*)d_in[15];
    const float* f6b  = (const float*)d_in[16];
    const float* f7w  = (const float*)d_in[17];
    const float* f7b  = (const float*)d_in[18];

    float* out = (float*)d_out;
    const size_t OFF_BE = 8192ull * 2048;
    const size_t OFF_LA = 2 * OFF_BE;
    const size_t OFF_LB = OFF_LA + 524288;
    const size_t OFF_Z  = OFF_LB + 524288;

    float *b0, *b1, *pre, *z, *wt, *bh;
    cudaGetSymbolAddress((void**)&b0,  g_buf0);
    cudaGetSymbolAddress((void**)&b1,  g_buf1);
    cudaGetSymbolAddress((void**)&pre, g_pre);
    cudaGetSymbolAddress((void**)&z,   g_z);
    cudaGetSymbolAddress((void**)&wt,  g_wt);
    cudaGetSymbolAddress((void**)&bh,  g_bh);

    constexpr int DYN = 2 * STAGEF * 4;   // 147456 bytes
    cudaFuncSetAttribute(mma_gemm<0>, cudaFuncAttributeMaxDynamicSharedMemorySize, DYN);
    cudaFuncSetAttribute(mma_gemm<1>, cudaFuncAttributeMaxDynamicSharedMemorySize, DYN);
    cudaFuncSetAttribute(mma_gemm<2>, cudaFuncAttributeMaxDynamicSharedMemorySize, DYN);

    // ---- weight prep (transpose to [N][K]) ----
    transpose_w<<<dim3(1024 / 32, 2048 / 32), 256>>>(f1w,  wt + OW1, 2048, 1024);
    transpose_w<<<dim3(1024 / 32, 1024 / 32), 256>>>(f2w,  wt + OW2, 1024, 1024);
    transpose_w<<<dim3(2048 / 32, 1024 / 32), 256>>>(f3w,  wt + OW3, 1024, 2048);
    transpose_w<<<dim3(  64 / 32, 2048 / 32), 256>>>(f41w, wt + OWH, 2048, 64);
    transpose_w<<<dim3(  64 / 32, 2048 / 32), 256>>>(f42w, wt + OWH + 64 * 2048, 2048, 64);
    transpose_w<<<dim3(2048 / 32,   64 / 32), 256>>>(f4w,  wt + OW4, 64, 2048);
    transpose_w<<<dim3(1024 / 32, 2048 / 32), 256>>>(f5w,  wt + OW5, 2048, 1024);
    transpose_w<<<dim3(1024 / 32, 1024 / 32), 256>>>(f6w,  wt + OW6, 1024, 1024);
    transpose_w<<<dim3(4096 / 32, 1024 / 32), 256>>>(f7w,  wt + OW7, 1024, 4096);
    concat_head_bias<<<1, 128>>>(f41b, f42b, bh);

    // ---- encoder ----
    mma_gemm<1><<<dim3( 8, 64), 256, DYN>>>(x,  wt + OW1, f1b, b0, nullptr, 2048, 1024);
    mma_gemm<1><<<dim3( 8, 64), 256, DYN>>>(b0, wt + OW2, f2b, b1, nullptr, 1024, 1024);
    mma_gemm<1><<<dim3(16, 64), 256, DYN>>>(b1, wt + OW3, f3b, b0, nullptr, 1024, 2048);
    // fused heads: N=128 (cols 0-63 = fc41, 64-127 = fc42)
    mma_gemm<0><<<dim3( 1, 64), 256, DYN>>>(b0, wt + OWH, bh, pre, nullptr, 2048, 128);
    // ---- gamma reparameterization ----
    gamma_sampler<<<(BATCHN * LATENT) / 256, 256>>>(
        pre, out + OFF_LA, out + OFF_LB, out + OFF_Z, z);
    // ---- decoder ----
    mma_gemm<1><<<dim3(16, 64), 256, DYN>>>(z,  wt + OW4, f4b, b1, nullptr, 64, 2048);
    mma_gemm<1><<<dim3( 8, 64), 256, DYN>>>(b1, wt + OW5, f5b, b0, nullptr, 2048, 1024);
    mma_gemm<1><<<dim3( 8, 64), 256, DYN>>>(b0, wt + OW6, f6b, b1, nullptr, 1024, 1024);
    // fc7 with fused softplus-split epilogue
    mma_gemm<2><<<dim3(32, 64), 256, DYN>>>(b1, wt + OW7, f7b, out, out + OFF_BE, 1024, 2048);
}

// round 5
// speedup vs baseline: 2.0041x; 1.2528x over previous
#include <cuda_runtime.h>
#include <cuda_fp16.h>
#include <cstdint>
#include <cstddef>

// ============================================================================
// VAE_gamma on GB300 via mma.sync m16n8k16.f16 with Markidis 2-way split
// (3 products: hi*hi + hi*lo + lo*hi => ~fp32-accurate GEMMs at fp16 rate),
// fused epilogues, JAX partitionable-threefry gamma sampler.
// ============================================================================

#define BATCHN   8192
#define LATENT   64
#define KROUNDS  24
#define GAMMA_N  524288u

// ---------------------------------------------------------------------------
// Scratch
// ---------------------------------------------------------------------------
__device__ float g_buf0[8192 * 2048];
__device__ float g_buf1[8192 * 2048];
__device__ float g_pre [8192 * 128];
__device__ float g_z   [8192 * 64];
__device__ float g_wt  [12976128];      // all transposed weights [N][K] fp32
__device__ float g_bh  [128];           // concat head bias

#define OW1  0u                         // [1024][2048]
#define OW2  (OW1 + 2097152u)           // [1024][1024]
#define OW3  (OW2 + 1048576u)           // [2048][1024]
#define OWH  (OW3 + 2097152u)           // [128][2048]
#define OW4  (OWH + 262144u)            // [2048][64]
#define OW5  (OW4 + 131072u)            // [1024][2048]
#define OW6  (OW5 + 2097152u)           // [1024][1024]
#define OW7  (OW6 + 1048576u)           // [4096][1024]

// ---------------------------------------------------------------------------
// Threefry-2x32 (JAX partitionable mode)
// ---------------------------------------------------------------------------
constexpr unsigned rotlc(unsigned x, int r) { return (x << r) | (x >> (32 - r)); }
constexpr unsigned long long tf_const(unsigned k0, unsigned k1,
                                      unsigned x0, unsigned x1) {
    unsigned kx = k0 ^ k1 ^ 0x1BD11BDAu;
    unsigned ks[3] = {k0, k1, kx};
    const int R0[4] = {13, 15, 26, 6};
    const int R1[4] = {17, 29, 16, 24};
    x0 += k0; x1 += k1;
    for (int i = 0; i < 5; i++) {
        const int* rr = (i % 2 == 0) ? R0 : R1;
        for (int j = 0; j < 4; j++) { x0 += x1; x1 = rotlc(x1, rr[j]); x1 ^= x0; }
        x0 += ks[(i + 1) % 3];
        x1 += ks[(i + 2) % 3] + (unsigned)(i + 1);
    }
    return ((unsigned long long)x0 << 32) | x1;
}
constexpr unsigned long long SPN = tf_const(0u, 42u, 0u, 0u);
constexpr unsigned long long SPU = tf_const(0u, 42u, 0u, 1u);
constexpr unsigned KEY_N0 = (unsigned)(SPN >> 32);
constexpr unsigned KEY_N1 = (unsigned)(SPN & 0xFFFFFFFFu);
constexpr unsigned KEY_U0 = (unsigned)(SPU >> 32);
constexpr unsigned KEY_U1 = (unsigned)(SPU & 0xFFFFFFFFu);

__device__ __forceinline__ uint32_t rotl32(uint32_t x, int r) {
    return __funnelshift_l(x, x, r);
}
__device__ __forceinline__ void tf2x32(uint32_t k0, uint32_t k1,
                                       uint32_t x0, uint32_t x1,
                                       uint32_t& y0, uint32_t& y1) {
    uint32_t kx = k0 ^ k1 ^ 0x1BD11BDAu;
    x0 += k0; x1 += k1;
#define TF_RND(r) { x0 += x1; x1 = rotl32(x1, r); x1 ^= x0; }
    TF_RND(13) TF_RND(15) TF_RND(26) TF_RND(6)   x0 += k1; x1 += kx + 1u;
    TF_RND(17) TF_RND(29) TF_RND(16) TF_RND(24)  x0 += kx; x1 += k0 + 2u;
    TF_RND(13) TF_RND(15) TF_RND(26) TF_RND(6)   x0 += k0; x1 += k1 + 3u;
    TF_RND(17) TF_RND(29) TF_RND(16) TF_RND(24)  x0 += k1; x1 += kx + 4u;
    TF_RND(13) TF_RND(15) TF_RND(26) TF_RND(6)   x0 += kx; x1 += k0 + 5u;
#undef TF_RND
    y0 = x0; y1 = x1;
}
__device__ __forceinline__ uint32_t gamma_bits(uint32_t k0, uint32_t k1,
                                               uint32_t idx) {
    uint32_t y0, y1;
    tf2x32(k0, k1, 0u, idx, y0, y1);
    return y0 ^ y1;
}
__device__ __forceinline__ float bits_to_u01(uint32_t bits) {
    return __uint_as_float((bits >> 9) | 0x3F800000u) - 1.0f;
}
__device__ __forceinline__ float erfinv_xla(float x) {
    float w = -log1pf(-__fmul_rn(x, x));
    float p;
    if (w < 5.0f) {
        w = __fadd_rn(w, -2.5f);
        p = 2.81022636e-08f;
        p = __fadd_rn(__fmul_rn(p, w),  3.43273939e-07f);
        p = __fadd_rn(__fmul_rn(p, w), -3.5233877e-06f);
        p = __fadd_rn(__fmul_rn(p, w), -4.39150654e-06f);
        p = __fadd_rn(__fmul_rn(p, w),  0.00021858087f);
        p = __fadd_rn(__fmul_rn(p, w), -0.00125372503f);
        p = __fadd_rn(__fmul_rn(p, w), -0.00417768164f);
        p = __fadd_rn(__fmul_rn(p, w),  0.246640727f);
        p = __fadd_rn(__fmul_rn(p, w),  1.50140941f);
    } else {
        w = __fadd_rn(__fsqrt_rn(w), -3.0f);
        p = -0.000200214257f;
        p = __fadd_rn(__fmul_rn(p, w),  0.000100950558f);
        p = __fadd_rn(__fmul_rn(p, w),  0.00134934322f);
        p = __fadd_rn(__fmul_rn(p, w), -0.00367342844f);
        p = __fadd_rn(__fmul_rn(p, w),  0.00573950773f);
        p = __fadd_rn(__fmul_rn(p, w), -0.0076224613f);
        p = __fadd_rn(__fmul_rn(p, w),  0.00943887047f);
        p = __fadd_rn(__fmul_rn(p, w),  1.00167406f);
        p = __fadd_rn(__fmul_rn(p, w),  2.83297682f);
    }
    return __fmul_rn(p, x);
}
__device__ __forceinline__ float softplusf(float x) {
    return __fadd_rn(fmaxf(x, 0.0f), log1pf(expf(-fabsf(x))));
}

// ---------------------------------------------------------------------------
// fp16 split helpers
// ---------------------------------------------------------------------------
__device__ __forceinline__ void split2(float x, float y,
                                       uint32_t& hi, uint32_t& lo) {
    __half2 h = __floats2half2_rn(x, y);
    float2 hf = __half22float2(h);
    __half2 l = __floats2half2_rn(__fadd_rn(x, -hf.x), __fadd_rn(y, -hf.y));
    hi = *reinterpret_cast<uint32_t*>(&h);
    lo = *reinterpret_cast<uint32_t*>(&l);
}
__device__ __forceinline__ void mma_f16(float* c, const uint32_t* a,
                                        const uint32_t* b) {
    asm volatile(
        "mma.sync.aligned.m16n8k16.row.col.f32.f16.f16.f32 "
        "{%0,%1,%2,%3}, {%4,%5,%6,%7}, {%8,%9}, {%0,%1,%2,%3};"
        : "+f"(c[0]), "+f"(c[1]), "+f"(c[2]), "+f"(c[3])
        : "r"(a[0]), "r"(a[1]), "r"(a[2]), "r"(a[3]),
          "r"(b[0]), "r"(b[1]));
}

// ---------------------------------------------------------------------------
// mma.sync fp16x2 GEMM: C[M,N] = act(A[M,K] @ Bt[N,K]^T + bias)
//   CTA tile 128x128, BK=32, 256 threads = 8 warps (2m x 4n), warp tile 64x32.
//   Planes of half2: [128 rows][20 half2]  (16 data + 4 pad: conflict-free)
//   ACT: 0 none, 1 relu, 2 softplus-split (fc7).
// ---------------------------------------------------------------------------
#define LDSK2  20                       // half2 per row (16 data + 4 pad)
#define PLANE2 (128 * LDSK2)            // half2 (=uint) per plane
#define STAGEU (4 * PLANE2)             // Ah Al Bh Bl

template <int ACT>
__global__ __launch_bounds__(256, 2)
void mma_gemm(const float* __restrict__ A, const float* __restrict__ Bt,
              const float* __restrict__ bias, float* __restrict__ C,
              float* __restrict__ C2, int K, int ldc) {
    extern __shared__ uint32_t sm[];
    __shared__ float s_bias[128];

    const int tid  = threadIdx.x;
    const int wid  = tid >> 5;
    const int lane = tid & 31;
    const int qr   = lane >> 2;         // 0..7
    const int qc   = lane & 3;          // 0..3
    const int m_w  = (wid >> 2) * 64;   // warp m offset
    const int n_w  = (wid & 3) * 32;    // warp n offset
    const int row0 = blockIdx.y * 128;
    const int col0 = blockIdx.x * 128;

    if (tid < 128) s_bias[tid] = bias[col0 + tid];

    float acc[4][4][4];
#pragma unroll
    for (int a = 0; a < 4; ++a)
#pragma unroll
        for (int b = 0; b < 4; ++b)
#pragma unroll
            for (int c = 0; c < 4; ++c) acc[a][b][c] = 0.0f;

    const int NCH = K >> 5;
    float4 av[4], bv[4];

    // thread's static store coords: idx = j*256+tid -> r=idx>>3, col2=(idx&7)*2
    // ---- prolog: load chunk 0, split, store to stage 0 ----
#pragma unroll
    for (int j = 0; j < 4; ++j) {
        int idx = j * 256 + tid;
        int r = idx >> 3, kq = (idx & 7) << 2;
        av[j] = *reinterpret_cast<const float4*>(&A [(size_t)(row0 + r) * K + kq]);
        bv[j] = *reinterpret_cast<const float4*>(&Bt[(size_t)(col0 + r) * K + kq]);
    }
    {
        uint32_t* Sa_h = sm;
        uint32_t* Sa_l = Sa_h + PLANE2;
        uint32_t* Sb_h = Sa_h + 2 * PLANE2;
        uint32_t* Sb_l = Sa_h + 3 * PLANE2;
#pragma unroll
        for (int j = 0; j < 4; ++j) {
            int idx = j * 256 + tid;
            int r = idx >> 3, c2 = (idx & 7) << 1;
            int off = r * LDSK2 + c2;
            uint32_t h0, l0, h1, l1;
            split2(av[j].x, av[j].y, h0, l0);
            split2(av[j].z, av[j].w, h1, l1);
            Sa_h[off] = h0; Sa_h[off + 1] = h1;
            Sa_l[off] = l0; Sa_l[off + 1] = l1;
            split2(bv[j].x, bv[j].y, h0, l0);
            split2(bv[j].z, bv[j].w, h1, l1);
            Sb_h[off] = h0; Sb_h[off + 1] = h1;
            Sb_l[off] = l0; Sb_l[off + 1] = l1;
        }
    }
    __syncthreads();

    for (int i = 0; i < NCH; ++i) {
        // prefetch next chunk into registers
        if (i + 1 < NCH) {
            int k0 = (i + 1) << 5;
#pragma unroll
            for (int j = 0; j < 4; ++j) {
                int idx = j * 256 + tid;
                int r = idx >> 3, kq = (idx & 7) << 2;
                av[j] = *reinterpret_cast<const float4*>(&A [(size_t)(row0 + r) * K + k0 + kq]);
                bv[j] = *reinterpret_cast<const float4*>(&Bt[(size_t)(col0 + r) * K + k0 + kq]);
            }
        }

        // compute on stage i&1 : 2 ksteps of k=16
        {
            const uint32_t* Sa_h = sm + (i & 1) * STAGEU;
            const uint32_t* Sa_l = Sa_h + PLANE2;
            const uint32_t* Sb_h = Sa_h + 2 * PLANE2;
            const uint32_t* Sb_l = Sa_h + 3 * PLANE2;
#pragma unroll
            for (int ks = 0; ks < 2; ++ks) {
                int kk2 = (ks << 3) + qc;   // half2 col
                uint32_t ah[4][4], al[4][4];
#pragma unroll
                for (int mt = 0; mt < 4; ++mt) {
                    int ro = (m_w + mt * 16 + qr) * LDSK2;
                    ah[mt][0] = Sa_h[ro + kk2];
                    ah[mt][1] = Sa_h[ro + 8 * LDSK2 + kk2];
                    ah[mt][2] = Sa_h[ro + kk2 + 4];
                    ah[mt][3] = Sa_h[ro + 8 * LDSK2 + kk2 + 4];
                    al[mt][0] = Sa_l[ro + kk2];
                    al[mt][1] = Sa_l[ro + 8 * LDSK2 + kk2];
                    al[mt][2] = Sa_l[ro + kk2 + 4];
                    al[mt][3] = Sa_l[ro + 8 * LDSK2 + kk2 + 4];
                }
                uint32_t bh[4][2], bl[4][2];
#pragma unroll
                for (int nt = 0; nt < 4; ++nt) {
                    int co = (n_w + nt * 8 + qr) * LDSK2 + kk2;
                    bh[nt][0] = Sb_h[co];
                    bh[nt][1] = Sb_h[co + 4];
                    bl[nt][0] = Sb_l[co];
                    bl[nt][1] = Sb_l[co + 4];
                }
#pragma unroll
                for (int mt = 0; mt < 4; ++mt)
#pragma unroll
                    for (int nt = 0; nt < 4; ++nt) {
                        mma_f16(acc[mt][nt], ah[mt], bh[nt]);
                        mma_f16(acc[mt][nt], ah[mt], bl[nt]);
                        mma_f16(acc[mt][nt], al[mt], bh[nt]);
                    }
            }
        }

        // split + store next chunk into the other stage
        if (i + 1 < NCH) {
            uint32_t* Sa_h = sm + ((i + 1) & 1) * STAGEU;
            uint32_t* Sa_l = Sa_h + PLANE2;
            uint32_t* Sb_h = Sa_h + 2 * PLANE2;
            uint32_t* Sb_l = Sa_h + 3 * PLANE2;
#pragma unroll
            for (int j = 0; j < 4; ++j) {
                int idx = j * 256 + tid;
                int r = idx >> 3, c2 = (idx & 7) << 1;
                int off = r * LDSK2 + c2;
                uint32_t h0, l0, h1, l1;
                split2(av[j].x, av[j].y, h0, l0);
                split2(av[j].z, av[j].w, h1, l1);
                Sa_h[off] = h0; Sa_h[off + 1] = h1;
                Sa_l[off] = l0; Sa_l[off + 1] = l1;
                split2(bv[j].x, bv[j].y, h0, l0);
                split2(bv[j].z, bv[j].w, h1, l1);
                Sb_h[off] = h0; Sb_h[off + 1] = h1;
                Sb_l[off] = l0; Sb_l[off + 1] = l1;
            }
            __syncthreads();
        }
    }

    // ---- epilogue: bias + activation, direct float2 stores ----
#pragma unroll
    for (int mt = 0; mt < 4; ++mt) {
        int r = row0 + m_w + mt * 16 + qr;
#pragma unroll
        for (int nt = 0; nt < 4; ++nt) {
            int lc = n_w + nt * 8 + 2 * qc;
            int gc = col0 + lc;
            float2 t0, t1;
            t0.x = acc[mt][nt][0] + s_bias[lc];
            t0.y = acc[mt][nt][1] + s_bias[lc + 1];
            t1.x = acc[mt][nt][2] + s_bias[lc];
            t1.y = acc[mt][nt][3] + s_bias[lc + 1];
            if (ACT == 1) {
                t0.x = fmaxf(t0.x, 0.0f); t0.y = fmaxf(t0.y, 0.0f);
                t1.x = fmaxf(t1.x, 0.0f); t1.y = fmaxf(t1.y, 0.0f);
            }
            if (ACT == 2) {
                t0.x = __fadd_rn(1e-6f, softplusf(t0.x));
                t0.y = __fadd_rn(1e-6f, softplusf(t0.y));
                t1.x = __fadd_rn(1e-6f, softplusf(t1.x));
                t1.y = __fadd_rn(1e-6f, softplusf(t1.y));
            }
            if (ACT == 2) {
                if (gc < 2048) {
                    *reinterpret_cast<float2*>(&C [(size_t)r * 2048 + gc]) = t0;
                    *reinterpret_cast<float2*>(&C [(size_t)(r + 8) * 2048 + gc]) = t1;
                } else {
                    *reinterpret_cast<float2*>(&C2[(size_t)r * 2048 + gc - 2048]) = t0;
                    *reinterpret_cast<float2*>(&C2[(size_t)(r + 8) * 2048 + gc - 2048]) = t1;
                }
            } else {
                *reinterpret_cast<float2*>(&C[(size_t)r * ldc + gc]) = t0;
                *reinterpret_cast<float2*>(&C[(size_t)(r + 8) * ldc + gc]) = t1;
            }
        }
    }
}

// ---------------------------------------------------------------------------
// Weight transpose prep: W[K,N] fp32 -> Wt[N,K] fp32
// ---------------------------------------------------------------------------
__global__ __launch_bounds__(256)
void transpose_w(const float* __restrict__ W, float* __restrict__ Wt,
                 int K, int N) {
    __shared__ float s[32][33];
    int n0 = blockIdx.x * 32, k0 = blockIdx.y * 32;
    int t = threadIdx.x;
    int a = t >> 5, b = t & 31;
#pragma unroll
    for (int p = 0; p < 4; ++p) {
        int k = p * 8 + a;
        s[k][b] = W[(size_t)(k0 + k) * N + n0 + b];
    }
    __syncthreads();
#pragma unroll
    for (int p = 0; p < 4; ++p) {
        int n = p * 8 + a;
        Wt[(size_t)(n0 + n) * K + k0 + b] = s[b][n];
    }
}

__global__ void concat_head_bias(const float* b1, const float* b2, float* o) {
    int t = threadIdx.x;
    o[t] = (t < 64) ? b1[t] : b2[t - 64];
}

// ---------------------------------------------------------------------------
// Gamma sampler (reads fused head buffer g_pre[row][0:64 | 64:128])
// ---------------------------------------------------------------------------
__global__ __launch_bounds__(256)
void gamma_sampler(const float* __restrict__ pre,
                   float* __restrict__ out_la, float* __restrict__ out_lb,
                   float* __restrict__ out_z,  float* __restrict__ z_buf) {
    int i = blockIdx.x * blockDim.x + threadIdx.x;
    if (i >= BATCHN * LATENT) return;
    int row = i >> 6, lat = i & 63;

    float al = __fadd_rn(1e-6f, softplusf(pre[row * 128 + lat]));
    float be = __fadd_rn(1e-6f, softplusf(pre[row * 128 + 64 + lat]));

    float d  = __fadd_rn(__fadd_rn(al, 1.0f), -(1.0f / 3.0f));
    float cc = __fdiv_rn(1.0f, __fsqrt_rn(__fmul_rn(9.0f, d)));

    const float LO     = -0.99999994f;
    const float SPAN_N = 2.0f;
    const float UMIN   = 1e-7f;
    const float SPAN_U = 1.0f - 1e-7f;
    const float SQRT2  = 1.41421356f;

    float eps_s = 0.0f, u_s = 0.0f, eps0 = 0.0f, u0 = 0.0f;
    bool found = false;

#pragma unroll 1
    for (int k = 0; k < KROUNDS; ++k) {
        uint32_t idx = (uint32_t)k * GAMMA_N + (uint32_t)i;
        uint32_t bn = gamma_bits(KEY_N0, KEY_N1, idx);
        uint32_t bu = gamma_bits(KEY_U0, KEY_U1, idx);

        float un = __fadd_rn(__fmul_rn(bits_to_u01(bn), SPAN_N), LO);
        un = fmaxf(LO, un);
        float eps = __fmul_rn(SQRT2, erfinv_xla(un));

        float uu = __fadd_rn(__fmul_rn(bits_to_u01(bu), SPAN_U), UMIN);
        uu = fmaxf(UMIN, uu);

        if (k == 0) { eps0 = eps; u0 = uu; }

        float v = __fadd_rn(1.0f, __fmul_rn(cc, eps));
        bool acc = false;
        if (v > 0.0f) {
            float e2 = __fmul_rn(eps, eps);
            float squeeze = __fadd_rn(1.0f, -__fmul_rn(__fmul_rn(0.0331f, e2), e2));
            if (uu < squeeze) {
                acc = true;
            } else {
                float v3 = __fmul_rn(__fmul_rn(v, v), v);
                float inner = __fadd_rn(__fadd_rn(1.0f, -v3), logf(v3));
                float rhs = __fadd_rn(__fmul_rn(__fmul_rn(0.5f, eps), eps),
                                      __fmul_rn(d, inner));
                if (logf(uu) < rhs) acc = true;
            }
        }
        if (acc) { eps_s = eps; u_s = uu; found = true; break; }
    }
    if (!found) { eps_s = eps0; u_s = u0; }

    float v1 = __fadd_rn(1.0f, __fmul_rn(cc, eps_s));
    float vs = __fmul_rn(v1, __fmul_rn(v1, v1));
    float t1 = logf(__fadd_rn(__fmul_rn(d, vs), 1e-6f));
    float t2 = __fdiv_rn(logf(__fadd_rn(u_s, 1e-6f)), __fadd_rn(al, 1e-6f));
    float z  = __fdiv_rn(expf(__fadd_rn(t1, t2)), __fadd_rn(be, 1e-6f));

    out_la[i] = al;
    out_lb[i] = be;
    out_z[i]  = z;
    z_buf[i]  = z;
}

// ---------------------------------------------------------------------------
// Launch
// ---------------------------------------------------------------------------
extern "C" void kernel_launch(void* const* d_in, const int* in_sizes, int n_in,
                              void* d_out, int out_size) {
    (void)in_sizes; (void)n_in; (void)out_size;

    const float* x    = (const float*)d_in[0];
    const float* f1w  = (const float*)d_in[1];
    const float* f1b  = (const float*)d_in[2];
    const float* f2w  = (const float*)d_in[3];
    const float* f2b  = (const float*)d_in[4];
    const float* f3w  = (const float*)d_in[5];
    const float* f3b  = (const float*)d_in[6];
    const float* f41w = (const float*)d_in[7];
    const float* f41b = (const float*)d_in[8];
    const float* f42w = (const float*)d_in[9];
    const float* f42b = (const float*)d_in[10];
    const float* f4w  = (const float*)d_in[11];
    const float* f4b  = (const float*)d_in[12];
    const float* f5w  = (const float*)d_in[13];
    const float* f5b  = (const float*)d_in[14];
    const float* f6w  = (const float*)d_in[15];
    const float* f6b  = (const float*)d_in[16];
    const float* f7w  = (const float*)d_in[17];
    const float* f7b  = (const float*)d_in[18];

    float* out = (float*)d_out;
    const size_t OFF_BE = 8192ull * 2048;
    const size_t OFF_LA = 2 * OFF_BE;
    const size_t OFF_LB = OFF_LA + 524288;
    const size_t OFF_Z  = OFF_LB + 524288;

    float *b0, *b1, *pre, *z, *wt, *bh;
    cudaGetSymbolAddress((void**)&b0,  g_buf0);
    cudaGetSymbolAddress((void**)&b1,  g_buf1);
    cudaGetSymbolAddress((void**)&pre, g_pre);
    cudaGetSymbolAddress((void**)&z,   g_z);
    cudaGetSymbolAddress((void**)&wt,  g_wt);
    cudaGetSymbolAddress((void**)&bh,  g_bh);

    constexpr int DYN = 2 * STAGEU * 4;   // 81920 bytes
    cudaFuncSetAttribute(mma_gemm<0>, cudaFuncAttributeMaxDynamicSharedMemorySize, DYN);
    cudaFuncSetAttribute(mma_gemm<1>, cudaFuncAttributeMaxDynamicSharedMemorySize, DYN);
    cudaFuncSetAttribute(mma_gemm<2>, cudaFuncAttributeMaxDynamicSharedMemorySize, DYN);

    // ---- weight prep (transpose to [N][K]) ----
    transpose_w<<<dim3(1024 / 32, 2048 / 32), 256>>>(f1w,  wt + OW1, 2048, 1024);
    transpose_w<<<dim3(1024 / 32, 1024 / 32), 256>>>(f2w,  wt + OW2, 1024, 1024);
    transpose_w<<<dim3(2048 / 32, 1024 / 32), 256>>>(f3w,  wt + OW3, 1024, 2048);
    transpose_w<<<dim3(  64 / 32, 2048 / 32), 256>>>(f41w, wt + OWH, 2048, 64);
    transpose_w<<<dim3(  64 / 32, 2048 / 32), 256>>>(f42w, wt + OWH + 64 * 2048, 2048, 64);
    transpose_w<<<dim3(2048 / 32,   64 / 32), 256>>>(f4w,  wt + OW4, 64, 2048);
    transpose_w<<<dim3(1024 / 32, 2048 / 32), 256>>>(f5w,  wt + OW5, 2048, 1024);
    transpose_w<<<dim3(1024 / 32, 1024 / 32), 256>>>(f6w,  wt + OW6, 1024, 1024);
    transpose_w<<<dim3(4096 / 32, 1024 / 32), 256>>>(f7w,  wt + OW7, 1024, 4096);
    concat_head_bias<<<1, 128>>>(f41b, f42b, bh);

    // ---- encoder ----
    mma_gemm<1><<<dim3( 8, 64), 256, DYN>>>(x,  wt + OW1, f1b, b0, nullptr, 2048, 1024);
    mma_gemm<1><<<dim3( 8, 64), 256, DYN>>>(b0, wt + OW2, f2b, b1, nullptr, 1024, 1024);
    mma_gemm<1><<<dim3(16, 64), 256, DYN>>>(b1, wt + OW3, f3b, b0, nullptr, 1024, 2048);
    // fused heads: N=128 (cols 0-63 = fc41, 64-127 = fc42)
    mma_gemm<0><<<dim3( 1, 64), 256, DYN>>>(b0, wt + OWH, bh, pre, nullptr, 2048, 128);
    // ---- gamma reparameterization ----
    gamma_sampler<<<(BATCHN * LATENT) / 256, 256>>>(
        pre, out + OFF_LA, out + OFF_LB, out + OFF_Z, z);
    // ---- decoder ----
    mma_gemm<1><<<dim3(16, 64), 256, DYN>>>(z,  wt + OW4, f4b, b1, nullptr, 64, 2048);
    mma_gemm<1><<<dim3( 8, 64), 256, DYN>>>(b1, wt + OW5, f5b, b0, nullptr, 2048, 1024);
    mma_gemm<1><<<dim3( 8, 64), 256, DYN>>>(b0, wt + OW6, f6b, b1, nullptr, 1024, 1024);
    // fc7 with fused softplus-split epilogue
    mma_gemm<2><<<dim3(32, 64), 256, DYN>>>(b1, wt + OW7, f7b, out, out + OFF_BE, 1024, 2048);
}

// round 6
// speedup vs baseline: 2.5501x; 1.2724x over previous
#include <cuda_runtime.h>
#include <cuda_fp16.h>
#include <cstdint>
#include <cstddef>

// ============================================================================
// VAE_gamma on GB300. GEMMs: mma.sync m16n8k16.f16, Markidis 2-way split
// (3 products => ~fp32 accuracy at fp16 rate). All operands pre-split into
// half hi/lo planes in gmem (weights at prep, activations in producer
// epilogues), cp.async gmem->smem, ldmatrix fragment loads.
// JAX partitionable-threefry gamma sampler.
// ============================================================================

#define BATCHN   8192
#define LATENT   64
#define KROUNDS  24
#define GAMMA_N  524288u

// ---------------------------------------------------------------------------
// Scratch (half hi/lo planes)
// ---------------------------------------------------------------------------
__device__ alignas(16) __half g_xh [8192 * 2048];
__device__ alignas(16) __half g_xl [8192 * 2048];
__device__ alignas(16) __half g_b0h[8192 * 2048];
__device__ alignas(16) __half g_b0l[8192 * 2048];
__device__ alignas(16) __half g_b1h[8192 * 2048];
__device__ alignas(16) __half g_b1l[8192 * 2048];
__device__ alignas(16) __half g_zh [8192 * 64];
__device__ alignas(16) __half g_zl [8192 * 64];
__device__ alignas(16) __half g_wh [12976128];
__device__ alignas(16) __half g_wl [12976128];
__device__ float g_pre[8192 * 128];
__device__ float g_bh [128];

#define OW1  0u                         // [1024][2048]
#define OW2  (OW1 + 2097152u)           // [1024][1024]
#define OW3  (OW2 + 1048576u)           // [2048][1024]
#define OWH  (OW3 + 2097152u)           // [128][2048]
#define OW4  (OWH + 262144u)            // [2048][64]
#define OW5  (OW4 + 131072u)            // [1024][2048]
#define OW6  (OW5 + 2097152u)           // [1024][1024]
#define OW7  (OW6 + 1048576u)           // [4096][1024]

// ---------------------------------------------------------------------------
// Threefry-2x32 (JAX partitionable mode)
// ---------------------------------------------------------------------------
constexpr unsigned rotlc(unsigned x, int r) { return (x << r) | (x >> (32 - r)); }
constexpr unsigned long long tf_const(unsigned k0, unsigned k1,
                                      unsigned x0, unsigned x1) {
    unsigned kx = k0 ^ k1 ^ 0x1BD11BDAu;
    unsigned ks[3] = {k0, k1, kx};
    const int R0[4] = {13, 15, 26, 6};
    const int R1[4] = {17, 29, 16, 24};
    x0 += k0; x1 += k1;
    for (int i = 0; i < 5; i++) {
        const int* rr = (i % 2 == 0) ? R0 : R1;
        for (int j = 0; j < 4; j++) { x0 += x1; x1 = rotlc(x1, rr[j]); x1 ^= x0; }
        x0 += ks[(i + 1) % 3];
        x1 += ks[(i + 2) % 3] + (unsigned)(i + 1);
    }
    return ((unsigned long long)x0 << 32) | x1;
}
constexpr unsigned long long SPN = tf_const(0u, 42u, 0u, 0u);
constexpr unsigned long long SPU = tf_const(0u, 42u, 0u, 1u);
constexpr unsigned KEY_N0 = (unsigned)(SPN >> 32);
constexpr unsigned KEY_N1 = (unsigned)(SPN & 0xFFFFFFFFu);
constexpr unsigned KEY_U0 = (unsigned)(SPU >> 32);
constexpr unsigned KEY_U1 = (unsigned)(SPU & 0xFFFFFFFFu);

__device__ __forceinline__ uint32_t rotl32(uint32_t x, int r) {
    return __funnelshift_l(x, x, r);
}
__device__ __forceinline__ void tf2x32(uint32_t k0, uint32_t k1,
                                       uint32_t x0, uint32_t x1,
                                       uint32_t& y0, uint32_t& y1) {
    uint32_t kx = k0 ^ k1 ^ 0x1BD11BDAu;
    x0 += k0; x1 += k1;
#define TF_RND(r) { x0 += x1; x1 = rotl32(x1, r); x1 ^= x0; }
    TF_RND(13) TF_RND(15) TF_RND(26) TF_RND(6)   x0 += k1; x1 += kx + 1u;
    TF_RND(17) TF_RND(29) TF_RND(16) TF_RND(24)  x0 += kx; x1 += k0 + 2u;
    TF_RND(13) TF_RND(15) TF_RND(26) TF_RND(6)   x0 += k0; x1 += k1 + 3u;
    TF_RND(17) TF_RND(29) TF_RND(16) TF_RND(24)  x0 += k1; x1 += kx + 4u;
    TF_RND(13) TF_RND(15) TF_RND(26) TF_RND(6)   x0 += kx; x1 += k0 + 5u;
#undef TF_RND
    y0 = x0; y1 = x1;
}
__device__ __forceinline__ uint32_t gamma_bits(uint32_t k0, uint32_t k1,
                                               uint32_t idx) {
    uint32_t y0, y1;
    tf2x32(k0, k1, 0u, idx, y0, y1);
    return y0 ^ y1;
}
__device__ __forceinline__ float bits_to_u01(uint32_t bits) {
    return __uint_as_float((bits >> 9) | 0x3F800000u) - 1.0f;
}
__device__ __forceinline__ float erfinv_xla(float x) {
    float w = -log1pf(-__fmul_rn(x, x));
    float p;
    if (w < 5.0f) {
        w = __fadd_rn(w, -2.5f);
        p = 2.81022636e-08f;
        p = __fadd_rn(__fmul_rn(p, w),  3.43273939e-07f);
        p = __fadd_rn(__fmul_rn(p, w), -3.5233877e-06f);
        p = __fadd_rn(__fmul_rn(p, w), -4.39150654e-06f);
        p = __fadd_rn(__fmul_rn(p, w),  0.00021858087f);
        p = __fadd_rn(__fmul_rn(p, w), -0.00125372503f);
        p = __fadd_rn(__fmul_rn(p, w), -0.00417768164f);
        p = __fadd_rn(__fmul_rn(p, w),  0.246640727f);
        p = __fadd_rn(__fmul_rn(p, w),  1.50140941f);
    } else {
        w = __fadd_rn(__fsqrt_rn(w), -3.0f);
        p = -0.000200214257f;
        p = __fadd_rn(__fmul_rn(p, w),  0.000100950558f);
        p = __fadd_rn(__fmul_rn(p, w),  0.00134934322f);
        p = __fadd_rn(__fmul_rn(p, w), -0.00367342844f);
        p = __fadd_rn(__fmul_rn(p, w),  0.00573950773f);
        p = __fadd_rn(__fmul_rn(p, w), -0.0076224613f);
        p = __fadd_rn(__fmul_rn(p, w),  0.00943887047f);
        p = __fadd_rn(__fmul_rn(p, w),  1.00167406f);
        p = __fadd_rn(__fmul_rn(p, w),  2.83297682f);
    }
    return __fmul_rn(p, x);
}
__device__ __forceinline__ float softplusf(float x) {
    return __fadd_rn(fmaxf(x, 0.0f), log1pf(expf(-fabsf(x))));
}

// ---------------------------------------------------------------------------
// mma / ldmatrix / cp.async helpers
// ---------------------------------------------------------------------------
__device__ __forceinline__ uint32_t smem_u32(const void* p) {
    uint32_t a;
    asm("{ .reg .u64 t; cvta.to.shared.u64 t, %1; cvt.u32.u64 %0, t; }"
        : "=r"(a) : "l"(p));
    return a;
}
__device__ __forceinline__ void mma_f16(float* c, const uint32_t* a,
                                        const uint32_t* b) {
    asm volatile(
        "mma.sync.aligned.m16n8k16.row.col.f32.f16.f16.f32 "
        "{%0,%1,%2,%3}, {%4,%5,%6,%7}, {%8,%9}, {%0,%1,%2,%3};"
        : "+f"(c[0]), "+f"(c[1]), "+f"(c[2]), "+f"(c[3])
        : "r"(a[0]), "r"(a[1]), "r"(a[2]), "r"(a[3]),
          "r"(b[0]), "r"(b[1]));
}
__device__ __forceinline__ void ldsm4(uint32_t& r0, uint32_t& r1,
                                      uint32_t& r2, uint32_t& r3, uint32_t a) {
    asm volatile("ldmatrix.sync.aligned.m8n8.x4.shared.b16 {%0,%1,%2,%3}, [%4];"
                 : "=r"(r0), "=r"(r1), "=r"(r2), "=r"(r3) : "r"(a));
}
__device__ __forceinline__ void cpa16(uint32_t dst, const void* src) {
    asm volatile("cp.async.ca.shared.global [%0], [%1], 16;"
                 :: "r"(dst), "l"(src));
}
__device__ __forceinline__ void split_h2(float x, float y,
                                         __half2& hi, __half2& lo) {
    hi = __floats2half2_rn(x, y);
    float2 b = __half22float2(hi);
    lo = __floats2half2_rn(__fadd_rn(x, -b.x), __fadd_rn(y, -b.y));
}

// ---------------------------------------------------------------------------
// GEMM: C[M,N] = act(A[M,K] @ Bt[N,K]^T + bias)
//   A,Bt given as half hi/lo planes. CTA 128x128, BK=32, 256 thr, 8 warps.
//   ACT: 0 -> fp32 C; 1 -> relu, write half hi/lo planes; 2 -> softplus-split.
// ---------------------------------------------------------------------------
#define PITCH2 40                        // halves per smem row (32 data + 8 pad)
#define PLANEH (128 * PITCH2)            // 5120 halves / plane
#define STAGEH (4 * PLANEH)              // 20480 halves = 40 KB / stage

template <int ACT>
__global__ __launch_bounds__(256, 2)
void mma_gemm(const __half* __restrict__ Ahg, const __half* __restrict__ Alg,
              const __half* __restrict__ Bhg, const __half* __restrict__ Blg,
              const float* __restrict__ bias,
              __half* __restrict__ Chg, __half* __restrict__ Clg,
              float* __restrict__ C, float* __restrict__ C2,
              int K, int ldc) {
    extern __shared__ __half smh[];
    __shared__ float s_bias[128];

    const int tid  = threadIdx.x;
    const int wid  = tid >> 5;
    const int lane = tid & 31;
    const int qr   = lane >> 2;
    const int qc   = lane & 3;
    const int grp  = lane >> 3;
    const int lr   = lane & 7;
    const int m_w  = (wid >> 2) * 64;
    const int n_w  = (wid & 3) * 32;
    const int row0 = blockIdx.y * 128;
    const int col0 = blockIdx.x * 128;

    if (tid < 128) s_bias[tid] = bias[col0 + tid];

    const uint32_t smb = smem_u32(smh);

    float acc[4][4][4];
#pragma unroll
    for (int a = 0; a < 4; ++a)
#pragma unroll
        for (int b = 0; b < 4; ++b)
#pragma unroll
            for (int c = 0; c < 4; ++c) acc[a][b][c] = 0.0f;

    const int NCH  = K >> 5;
    const int r_ld = tid >> 1;
    const int q0   = (tid & 1) * 2;      // 16B-quad base within row

    const __half* srcs[4] = { Ahg, Alg, Bhg, Blg };
    const int growA = row0 + r_ld;
    const int growB = col0 + r_ld;

    // ---- cp.async issue for one stage ----
    auto issue = [&](int stage, int k0) {
        uint32_t dbase = smb + (uint32_t)((stage * STAGEH + r_ld * PITCH2 + q0 * 8) * 2);
#pragma unroll
        for (int p = 0; p < 4; ++p) {
            int grow = (p < 2) ? growA : growB;
            const __half* s = srcs[p] + (size_t)grow * K + k0 + q0 * 8;
            uint32_t d = dbase + (uint32_t)(p * PLANEH * 2);
            cpa16(d, s);
            cpa16(d + 16, s + 8);
        }
        asm volatile("cp.async.commit_group;" ::: "memory");
    };

    issue(0, 0);
    for (int i = 0; i < NCH; ++i) {
        if (i + 1 < NCH) {
            issue((i + 1) & 1, (i + 1) << 5);
            asm volatile("cp.async.wait_group 1;" ::: "memory");
        } else {
            asm volatile("cp.async.wait_group 0;" ::: "memory");
        }
        __syncthreads();

        const uint32_t sb = smb + (uint32_t)(((i & 1) * STAGEH) * 2);
#pragma unroll
        for (int ks = 0; ks < 2; ++ks) {
            uint32_t bh[4][2], bl[4][2];
#pragma unroll
            for (int nn = 0; nn < 2; ++nn) {
                uint32_t ah_ = sb + (uint32_t)(((2 * PLANEH) +
                    (n_w + nn * 16 + (grp >> 1) * 8 + lr) * PITCH2 +
                    ks * 16 + (grp & 1) * 8) * 2);
                ldsm4(bh[2 * nn][0], bh[2 * nn][1],
                      bh[2 * nn + 1][0], bh[2 * nn + 1][1], ah_);
                ldsm4(bl[2 * nn][0], bl[2 * nn][1],
                      bl[2 * nn + 1][0], bl[2 * nn + 1][1],
                      ah_ + (uint32_t)(PLANEH * 2));
            }
#pragma unroll
            for (int mt = 0; mt < 4; ++mt) {
                uint32_t ah[4], al[4];
                uint32_t aaddr = sb + (uint32_t)((
                    (m_w + mt * 16 + (grp & 1) * 8 + lr) * PITCH2 +
                    ks * 16 + (grp >> 1) * 8) * 2);
                ldsm4(ah[0], ah[1], ah[2], ah[3], aaddr);
                ldsm4(al[0], al[1], al[2], al[3], aaddr + (uint32_t)(PLANEH * 2));
#pragma unroll
                for (int nt = 0; nt < 4; ++nt) {
                    mma_f16(acc[mt][nt], ah, bh[nt]);
                    mma_f16(acc[mt][nt], ah, bl[nt]);
                    mma_f16(acc[mt][nt], al, bh[nt]);
                }
            }
        }
        __syncthreads();
    }

    // ---- epilogue ----
#pragma unroll
    for (int mt = 0; mt < 4; ++mt) {
        int r = row0 + m_w + mt * 16 + qr;
#pragma unroll
        for (int nt = 0; nt < 4; ++nt) {
            int lc = n_w + nt * 8 + 2 * qc;
            int gc = col0 + lc;
            float2 t0, t1;
            t0.x = acc[mt][nt][0] + s_bias[lc];
            t0.y = acc[mt][nt][1] + s_bias[lc + 1];
            t1.x = acc[mt][nt][2] + s_bias[lc];
            t1.y = acc[mt][nt][3] + s_bias[lc + 1];
            if (ACT == 1) {
                t0.x = fmaxf(t0.x, 0.0f); t0.y = fmaxf(t0.y, 0.0f);
                t1.x = fmaxf(t1.x, 0.0f); t1.y = fmaxf(t1.y, 0.0f);
                __half2 h2, l2;
                split_h2(t0.x, t0.y, h2, l2);
                *reinterpret_cast<__half2*>(&Chg[(size_t)r * ldc + gc]) = h2;
                *reinterpret_cast<__half2*>(&Clg[(size_t)r * ldc + gc]) = l2;
                split_h2(t1.x, t1.y, h2, l2);
                *reinterpret_cast<__half2*>(&Chg[(size_t)(r + 8) * ldc + gc]) = h2;
                *reinterpret_cast<__half2*>(&Clg[(size_t)(r + 8) * ldc + gc]) = l2;
            } else if (ACT == 2) {
                t0.x = __fadd_rn(1e-6f, softplusf(t0.x));
                t0.y = __fadd_rn(1e-6f, softplusf(t0.y));
                t1.x = __fadd_rn(1e-6f, softplusf(t1.x));
                t1.y = __fadd_rn(1e-6f, softplusf(t1.y));
                if (gc < 2048) {
                    *reinterpret_cast<float2*>(&C [(size_t)r * 2048 + gc]) = t0;
                    *reinterpret_cast<float2*>(&C [(size_t)(r + 8) * 2048 + gc]) = t1;
                } else {
                    *reinterpret_cast<float2*>(&C2[(size_t)r * 2048 + gc - 2048]) = t0;
                    *reinterpret_cast<float2*>(&C2[(size_t)(r + 8) * 2048 + gc - 2048]) = t1;
                }
            } else {
                *reinterpret_cast<float2*>(&C[(size_t)r * ldc + gc]) = t0;
                *reinterpret_cast<float2*>(&C[(size_t)(r + 8) * ldc + gc]) = t1;
            }
        }
    }
}

// ---------------------------------------------------------------------------
// Prep: transpose + split weights W[K,N] fp32 -> Wh/Wl [N][K] half
// ---------------------------------------------------------------------------
__global__ __launch_bounds__(256)
void transpose_w_split(const float* __restrict__ W, __half* __restrict__ Wh,
                       __half* __restrict__ Wl, int K, int N) {
    __shared__ float s[32][33];
    int n0 = blockIdx.x * 32, k0 = blockIdx.y * 32;
    int t = threadIdx.x;
    int a = t >> 5, b = t & 31;
#pragma unroll
    for (int p = 0; p < 4; ++p) {
        int k = p * 8 + a;
        s[k][b] = W[(size_t)(k0 + k) * N + n0 + b];
    }
    __syncthreads();
#pragma unroll
    for (int p = 0; p < 4; ++p) {
        int n = p * 8 + a;
        float v = s[b][n];
        __half h = __float2half_rn(v);
        Wh[(size_t)(n0 + n) * K + k0 + b] = h;
        Wl[(size_t)(n0 + n) * K + k0 + b] =
            __float2half_rn(__fadd_rn(v, -__half2float(h)));
    }
}

// split fp32 activations -> half hi/lo planes (for x)
__global__ __launch_bounds__(256)
void split_act(const float* __restrict__ X, __half* __restrict__ Xh,
               __half* __restrict__ Xl, int n4) {
    int t = blockIdx.x * blockDim.x + threadIdx.x;
    if (t >= n4) return;
    float4 v = reinterpret_cast<const float4*>(X)[t];
    __half2 h0, l0, h1, l1;
    split_h2(v.x, v.y, h0, l0);
    split_h2(v.z, v.w, h1, l1);
    reinterpret_cast<__half2*>(Xh)[2 * t]     = h0;
    reinterpret_cast<__half2*>(Xh)[2 * t + 1] = h1;
    reinterpret_cast<__half2*>(Xl)[2 * t]     = l0;
    reinterpret_cast<__half2*>(Xl)[2 * t + 1] = l1;
}

__global__ void concat_head_bias(const float* b1, const float* b2, float* o) {
    int t = threadIdx.x;
    o[t] = (t < 64) ? b1[t] : b2[t - 64];
}

// ---------------------------------------------------------------------------
// Gamma sampler (reads fused head buffer g_pre[row][0:64 | 64:128])
// ---------------------------------------------------------------------------
__global__ __launch_bounds__(256)
void gamma_sampler(const float* __restrict__ pre,
                   float* __restrict__ out_la, float* __restrict__ out_lb,
                   float* __restrict__ out_z,
                   __half* __restrict__ zh, __half* __restrict__ zl) {
    int i = blockIdx.x * blockDim.x + threadIdx.x;
    if (i >= BATCHN * LATENT) return;
    int row = i >> 6, lat = i & 63;

    float al = __fadd_rn(1e-6f, softplusf(pre[row * 128 + lat]));
    float be = __fadd_rn(1e-6f, softplusf(pre[row * 128 + 64 + lat]));

    float d  = __fadd_rn(__fadd_rn(al, 1.0f), -(1.0f / 3.0f));
    float cc = __fdiv_rn(1.0f, __fsqrt_rn(__fmul_rn(9.0f, d)));

    const float LO     = -0.99999994f;
    const float SPAN_N = 2.0f;
    const float UMIN   = 1e-7f;
    const float SPAN_U = 1.0f - 1e-7f;
    const float SQRT2  = 1.41421356f;

    float eps_s = 0.0f, u_s = 0.0f, eps0 = 0.0f, u0 = 0.0f;
    bool found = false;

#pragma unroll 1
    for (int k = 0; k < KROUNDS; ++k) {
        uint32_t idx = (uint32_t)k * GAMMA_N + (uint32_t)i;
        uint32_t bn = gamma_bits(KEY_N0, KEY_N1, idx);
        uint32_t bu = gamma_bits(KEY_U0, KEY_U1, idx);

        float un = __fadd_rn(__fmul_rn(bits_to_u01(bn), SPAN_N), LO);
        un = fmaxf(LO, un);
        float eps = __fmul_rn(SQRT2, erfinv_xla(un));

        float uu = __fadd_rn(__fmul_rn(bits_to_u01(bu), SPAN_U), UMIN);
        uu = fmaxf(UMIN, uu);

        if (k == 0) { eps0 = eps; u0 = uu; }

        float v = __fadd_rn(1.0f, __fmul_rn(cc, eps));
        bool acc = false;
        if (v > 0.0f) {
            float e2 = __fmul_rn(eps, eps);
            float squeeze = __fadd_rn(1.0f, -__fmul_rn(__fmul_rn(0.0331f, e2), e2));
            if (uu < squeeze) {
                acc = true;
            } else {
                float v3 = __fmul_rn(__fmul_rn(v, v), v);
                float inner = __fadd_rn(__fadd_rn(1.0f, -v3), logf(v3));
                float rhs = __fadd_rn(__fmul_rn(__fmul_rn(0.5f, eps), eps),
                                      __fmul_rn(d, inner));
                if (logf(uu) < rhs) acc = true;
            }
        }
        if (acc) { eps_s = eps; u_s = uu; found = true; break; }
    }
    if (!found) { eps_s = eps0; u_s = u0; }

    float v1 = __fadd_rn(1.0f, __fmul_rn(cc, eps_s));
    float vs = __fmul_rn(v1, __fmul_rn(v1, v1));
    float t1 = logf(__fadd_rn(__fmul_rn(d, vs), 1e-6f));
    float t2 = __fdiv_rn(logf(__fadd_rn(u_s, 1e-6f)), __fadd_rn(al, 1e-6f));
    float z  = __fdiv_rn(expf(__fadd_rn(t1, t2)), __fadd_rn(be, 1e-6f));

    out_la[i] = al;
    out_lb[i] = be;
    out_z[i]  = z;
    __half hz = __float2half_rn(z);
    zh[i] = hz;
    zl[i] = __float2half_rn(__fadd_rn(z, -__half2float(hz)));
}

// ---------------------------------------------------------------------------
// Launch
// ---------------------------------------------------------------------------
extern "C" void kernel_launch(void* const* d_in, const int* in_sizes, int n_in,
                              void* d_out, int out_size) {
    (void)in_sizes; (void)n_in; (void)out_size;

    const float* x    = (const float*)d_in[0];
    const float* f1w  = (const float*)d_in[1];
    const float* f1b  = (const float*)d_in[2];
    const float* f2w  = (const float*)d_in[3];
    const float* f2b  = (const float*)d_in[4];
    const float* f3w  = (const float*)d_in[5];
    const float* f3b  = (const float*)d_in[6];
    const float* f41w = (const float*)d_in[7];
    const float* f41b = (const float*)d_in[8];
    const float* f42w = (const float*)d_in[9];
    const float* f42b = (const float*)d_in[10];
    const float* f4w  = (const float*)d_in[11];
    const float* f4b  = (const float*)d_in[12];
    const float* f5w  = (const float*)d_in[13];
    const float* f5b  = (const float*)d_in[14];
    const float* f6w  = (const float*)d_in[15];
    const float* f6b  = (const float*)d_in[16];
    const float* f7w  = (const float*)d_in[17];
    const float* f7b  = (const float*)d_in[18];

    float* out = (float*)d_out;
    const size_t OFF_BE = 8192ull * 2048;
    const size_t OFF_LA = 2 * OFF_BE;
    const size_t OFF_LB = OFF_LA + 524288;
    const size_t OFF_Z  = OFF_LB + 524288;

    __half *xh, *xl, *b0h, *b0l, *b1h, *b1l, *zh, *zl, *wh, *wl;
    float *pre, *bh;
    cudaGetSymbolAddress((void**)&xh,  g_xh);
    cudaGetSymbolAddress((void**)&xl,  g_xl);
    cudaGetSymbolAddress((void**)&b0h, g_b0h);
    cudaGetSymbolAddress((void**)&b0l, g_b0l);
    cudaGetSymbolAddress((void**)&b1h, g_b1h);
    cudaGetSymbolAddress((void**)&b1l, g_b1l);
    cudaGetSymbolAddress((void**)&zh,  g_zh);
    cudaGetSymbolAddress((void**)&zl,  g_zl);
    cudaGetSymbolAddress((void**)&wh,  g_wh);
    cudaGetSymbolAddress((void**)&wl,  g_wl);
    cudaGetSymbolAddress((void**)&pre, g_pre);
    cudaGetSymbolAddress((void**)&bh,  g_bh);

    constexpr int DYN = 2 * STAGEH * 2;   // 81920 bytes
    cudaFuncSetAttribute(mma_gemm<0>, cudaFuncAttributeMaxDynamicSharedMemorySize, DYN);
    cudaFuncSetAttribute(mma_gemm<1>, cudaFuncAttributeMaxDynamicSharedMemorySize, DYN);
    cudaFuncSetAttribute(mma_gemm<2>, cudaFuncAttributeMaxDynamicSharedMemorySize, DYN);

    // ---- prep: transpose+split weights, split x ----
    transpose_w_split<<<dim3(1024 / 32, 2048 / 32), 256>>>(f1w,  wh + OW1, wl + OW1, 2048, 1024);
    transpose_w_split<<<dim3(1024 / 32, 1024 / 32), 256>>>(f2w,  wh + OW2, wl + OW2, 1024, 1024);
    transpose_w_split<<<dim3(2048 / 32, 1024 / 32), 256>>>(f3w,  wh + OW3, wl + OW3, 1024, 2048);
    transpose_w_split<<<dim3(  64 / 32, 2048 / 32), 256>>>(f41w, wh + OWH, wl + OWH, 2048, 64);
    transpose_w_split<<<dim3(  64 / 32, 2048 / 32), 256>>>(f42w, wh + OWH + 64 * 2048, wl + OWH + 64 * 2048, 2048, 64);
    transpose_w_split<<<dim3(2048 / 32,   64 / 32), 256>>>(f4w,  wh + OW4, wl + OW4, 64, 2048);
    transpose_w_split<<<dim3(1024 / 32, 2048 / 32), 256>>>(f5w,  wh + OW5, wl + OW5, 2048, 1024);
    transpose_w_split<<<dim3(1024 / 32, 1024 / 32), 256>>>(f6w,  wh + OW6, wl + OW6, 1024, 1024);
    transpose_w_split<<<dim3(4096 / 32, 1024 / 32), 256>>>(f7w,  wh + OW7, wl + OW7, 1024, 4096);
    concat_head_bias<<<1, 128>>>(f41b, f42b, bh);
    split_act<<<(8192 * 2048 / 4) / 256, 256>>>(x, xh, xl, 8192 * 2048 / 4);

    // ---- encoder ----
    mma_gemm<1><<<dim3( 8, 64), 256, DYN>>>(xh,  xl,  wh + OW1, wl + OW1, f1b, b0h, b0l, nullptr, nullptr, 2048, 1024);
    mma_gemm<1><<<dim3( 8, 64), 256, DYN>>>(b0h, b0l, wh + OW2, wl + OW2, f2b, b1h, b1l, nullptr, nullptr, 1024, 1024);
    mma_gemm<1><<<dim3(16, 64), 256, DYN>>>(b1h, b1l, wh + OW3, wl + OW3, f3b, b0h, b0l, nullptr, nullptr, 1024, 2048);
    // fused heads: N=128 (cols 0-63 = fc41, 64-127 = fc42) -> fp32 pre
    mma_gemm<0><<<dim3( 1, 64), 256, DYN>>>(b0h, b0l, wh + OWH, wl + OWH, bh, nullptr, nullptr, pre, nullptr, 2048, 128);
    // ---- gamma reparameterization ----
    gamma_sampler<<<(BATCHN * LATENT) / 256, 256>>>(
        pre, out + OFF_LA, out + OFF_LB, out + OFF_Z, zh, zl);
    // ---- decoder ----
    mma_gemm<1><<<dim3(16, 64), 256, DYN>>>(zh,  zl,  wh + OW4, wl + OW4, f4b, b1h, b1l, nullptr, nullptr, 64, 2048);
    mma_gemm<1><<<dim3( 8, 64), 256, DYN>>>(b1h, b1l, wh + OW5, wl + OW5, f5b, b0h, b0l, nullptr, nullptr, 2048, 1024);
    mma_gemm<1><<<dim3( 8, 64), 256, DYN>>>(b0h, b0l, wh + OW6, wl + OW6, f6b, b1h, b1l, nullptr, nullptr, 1024, 1024);
    // fc7 with fused softplus-split epilogue -> fp32 outputs
    mma_gemm<2><<<dim3(32, 64), 256, DYN>>>(b1h, b1l, wh + OW7, wl + OW7, f7b, nullptr, nullptr, out, out + OFF_BE, 1024, 2048);
}

// round 7
// speedup vs baseline: 2.6278x; 1.0305x over previous
#include <cuda_runtime.h>
#include <cuda_fp16.h>
#include <cstdint>
#include <cstddef>

// ============================================================================
// VAE_gamma on GB300. GEMMs: mma.sync m16n8k16.f16, Markidis 2-way split
// (3 products => ~fp32 accuracy). Pre-split half hi/lo operand planes in gmem,
// cp.async.cg 3-stage pipeline (1 barrier/chunk), XOR-swizzled smem,
// ldmatrix fragment loads. JAX partitionable-threefry gamma sampler.
// ============================================================================

#define BATCHN   8192
#define LATENT   64
#define KROUNDS  24
#define GAMMA_N  524288u

// ---------------------------------------------------------------------------
// Scratch (half hi/lo planes)
// ---------------------------------------------------------------------------
__device__ alignas(16) __half g_xh [8192 * 2048];
__device__ alignas(16) __half g_xl [8192 * 2048];
__device__ alignas(16) __half g_b0h[8192 * 2048];
__device__ alignas(16) __half g_b0l[8192 * 2048];
__device__ alignas(16) __half g_b1h[8192 * 2048];
__device__ alignas(16) __half g_b1l[8192 * 2048];
__device__ alignas(16) __half g_zh [8192 * 64];
__device__ alignas(16) __half g_zl [8192 * 64];
__device__ alignas(16) __half g_wh [12976128];
__device__ alignas(16) __half g_wl [12976128];
__device__ float g_pre[8192 * 128];
__device__ float g_bh [128];

#define OW1  0u                         // [1024][2048]
#define OW2  (OW1 + 2097152u)           // [1024][1024]
#define OW3  (OW2 + 1048576u)           // [2048][1024]
#define OWH  (OW3 + 2097152u)           // [128][2048]
#define OW4  (OWH + 262144u)            // [2048][64]
#define OW5  (OW4 + 131072u)            // [1024][2048]
#define OW6  (OW5 + 2097152u)           // [1024][1024]
#define OW7  (OW6 + 1048576u)           // [4096][1024]

// ---------------------------------------------------------------------------
// Threefry-2x32 (JAX partitionable mode)
// ---------------------------------------------------------------------------
constexpr unsigned rotlc(unsigned x, int r) { return (x << r) | (x >> (32 - r)); }
constexpr unsigned long long tf_const(unsigned k0, unsigned k1,
                                      unsigned x0, unsigned x1) {
    unsigned kx = k0 ^ k1 ^ 0x1BD11BDAu;
    unsigned ks[3] = {k0, k1, kx};
    const int R0[4] = {13, 15, 26, 6};
    const int R1[4] = {17, 29, 16, 24};
    x0 += k0; x1 += k1;
    for (int i = 0; i < 5; i++) {
        const int* rr = (i % 2 == 0) ? R0 : R1;
        for (int j = 0; j < 4; j++) { x0 += x1; x1 = rotlc(x1, rr[j]); x1 ^= x0; }
        x0 += ks[(i + 1) % 3];
        x1 += ks[(i + 2) % 3] + (unsigned)(i + 1);
    }
    return ((unsigned long long)x0 << 32) | x1;
}
constexpr unsigned long long SPN = tf_const(0u, 42u, 0u, 0u);
constexpr unsigned long long SPU = tf_const(0u, 42u, 0u, 1u);
constexpr unsigned KEY_N0 = (unsigned)(SPN >> 32);
constexpr unsigned KEY_N1 = (unsigned)(SPN & 0xFFFFFFFFu);
constexpr unsigned KEY_U0 = (unsigned)(SPU >> 32);
constexpr unsigned KEY_U1 = (unsigned)(SPU & 0xFFFFFFFFu);

__device__ __forceinline__ uint32_t rotl32(uint32_t x, int r) {
    return __funnelshift_l(x, x, r);
}
__device__ __forceinline__ void tf2x32(uint32_t k0, uint32_t k1,
                                       uint32_t x0, uint32_t x1,
                                       uint32_t& y0, uint32_t& y1) {
    uint32_t kx = k0 ^ k1 ^ 0x1BD11BDAu;
    x0 += k0; x1 += k1;
#define TF_RND(r) { x0 += x1; x1 = rotl32(x1, r); x1 ^= x0; }
    TF_RND(13) TF_RND(15) TF_RND(26) TF_RND(6)   x0 += k1; x1 += kx + 1u;
    TF_RND(17) TF_RND(29) TF_RND(16) TF_RND(24)  x0 += kx; x1 += k0 + 2u;
    TF_RND(13) TF_RND(15) TF_RND(26) TF_RND(6)   x0 += k0; x1 += k1 + 3u;
    TF_RND(17) TF_RND(29) TF_RND(16) TF_RND(24)  x0 += k1; x1 += kx + 4u;
    TF_RND(13) TF_RND(15) TF_RND(26) TF_RND(6)   x0 += kx; x1 += k0 + 5u;
#undef TF_RND
    y0 = x0; y1 = x1;
}
__device__ __forceinline__ uint32_t gamma_bits(uint32_t k0, uint32_t k1,
                                               uint32_t idx) {
    uint32_t y0, y1;
    tf2x32(k0, k1, 0u, idx, y0, y1);
    return y0 ^ y1;
}
__device__ __forceinline__ float bits_to_u01(uint32_t bits) {
    return __uint_as_float((bits >> 9) | 0x3F800000u) - 1.0f;
}
__device__ __forceinline__ float erfinv_xla(float x) {
    float w = -log1pf(-__fmul_rn(x, x));
    float p;
    if (w < 5.0f) {
        w = __fadd_rn(w, -2.5f);
        p = 2.81022636e-08f;
        p = __fadd_rn(__fmul_rn(p, w),  3.43273939e-07f);
        p = __fadd_rn(__fmul_rn(p, w), -3.5233877e-06f);
        p = __fadd_rn(__fmul_rn(p, w), -4.39150654e-06f);
        p = __fadd_rn(__fmul_rn(p, w),  0.00021858087f);
        p = __fadd_rn(__fmul_rn(p, w), -0.00125372503f);
        p = __fadd_rn(__fmul_rn(p, w), -0.00417768164f);
        p = __fadd_rn(__fmul_rn(p, w),  0.246640727f);
        p = __fadd_rn(__fmul_rn(p, w),  1.50140941f);
    } else {
        w = __fadd_rn(__fsqrt_rn(w), -3.0f);
        p = -0.000200214257f;
        p = __fadd_rn(__fmul_rn(p, w),  0.000100950558f);
        p = __fadd_rn(__fmul_rn(p, w),  0.00134934322f);
        p = __fadd_rn(__fmul_rn(p, w), -0.00367342844f);
        p = __fadd_rn(__fmul_rn(p, w),  0.00573950773f);
        p = __fadd_rn(__fmul_rn(p, w), -0.0076224613f);
        p = __fadd_rn(__fmul_rn(p, w),  0.00943887047f);
        p = __fadd_rn(__fmul_rn(p, w),  1.00167406f);
        p = __fadd_rn(__fmul_rn(p, w),  2.83297682f);
    }
    return __fmul_rn(p, x);
}
__device__ __forceinline__ float softplusf(float x) {
    return __fadd_rn(fmaxf(x, 0.0f), log1pf(expf(-fabsf(x))));
}

// ---------------------------------------------------------------------------
// mma / ldmatrix / cp.async helpers
// ---------------------------------------------------------------------------
__device__ __forceinline__ uint32_t smem_u32(const void* p) {
    uint32_t a;
    asm("{ .reg .u64 t; cvta.to.shared.u64 t, %1; cvt.u32.u64 %0, t; }"
        : "=r"(a) : "l"(p));
    return a;
}
__device__ __forceinline__ void mma_f16(float* c, const uint32_t* a,
                                        const uint32_t* b) {
    asm volatile(
        "mma.sync.aligned.m16n8k16.row.col.f32.f16.f16.f32 "
        "{%0,%1,%2,%3}, {%4,%5,%6,%7}, {%8,%9}, {%0,%1,%2,%3};"
        : "+f"(c[0]), "+f"(c[1]), "+f"(c[2]), "+f"(c[3])
        : "r"(a[0]), "r"(a[1]), "r"(a[2]), "r"(a[3]),
          "r"(b[0]), "r"(b[1]));
}
__device__ __forceinline__ void ldsm4(uint32_t& r0, uint32_t& r1,
                                      uint32_t& r2, uint32_t& r3, uint32_t a) {
    asm volatile("ldmatrix.sync.aligned.m8n8.x4.shared.b16 {%0,%1,%2,%3}, [%4];"
                 : "=r"(r0), "=r"(r1), "=r"(r2), "=r"(r3) : "r"(a));
}
__device__ __forceinline__ void cpa16(uint32_t dst, const void* src) {
    asm volatile("cp.async.cg.shared.global [%0], [%1], 16;"
                 :: "r"(dst), "l"(src));
}
__device__ __forceinline__ void split_h2(float x, float y,
                                         __half2& hi, __half2& lo) {
    hi = __floats2half2_rn(x, y);
    float2 b = __half22float2(hi);
    lo = __floats2half2_rn(__fadd_rn(x, -b.x), __fadd_rn(y, -b.y));
}
// XOR-swizzled smem byte offset within an 8KB plane:
//   logical (row 0..127, quad 0..3 of 16B); pair-line = 128B.
__device__ __forceinline__ uint32_t swz(int row, int q) {
    return (uint32_t)(((row >> 1) << 7) +
                      (((((row & 1) << 2) | q) ^ ((row >> 1) & 7)) << 4));
}

// ---------------------------------------------------------------------------
// GEMM: C[M,N] = act(A[M,K] @ Bt[N,K]^T + bias)
//   A,Bt as half hi/lo planes. CTA 128x128, BK=32, 256 thr, 8 warps (2x4).
//   3-stage cp.async pipeline, one __syncthreads per chunk.
//   ACT: 0 -> fp32 C; 1 -> relu, half hi/lo planes; 2 -> softplus-split fp32.
// ---------------------------------------------------------------------------
#define PLANEB 8192                     // bytes per plane (128 x 64B)
#define STAGEB (4 * PLANEB)             // Ah Al Bh Bl = 32 KB
#define NSTAGE 3

template <int ACT>
__global__ __launch_bounds__(256, 2)
void mma_gemm(const __half* __restrict__ Ahg, const __half* __restrict__ Alg,
              const __half* __restrict__ Bhg, const __half* __restrict__ Blg,
              const float* __restrict__ bias,
              __half* __restrict__ Chg, __half* __restrict__ Clg,
              float* __restrict__ C, float* __restrict__ C2,
              int K, int ldc) {
    extern __shared__ __half smh[];
    __shared__ float s_bias[128];

    const int tid  = threadIdx.x;
    const int wid  = tid >> 5;
    const int lane = tid & 31;
    const int qr   = lane >> 2;
    const int qc   = lane & 3;
    const int grp  = lane >> 3;
    const int lr   = lane & 7;
    const int m_w  = (wid >> 2) * 64;
    const int n_w  = (wid & 3) * 32;
    const int row0 = blockIdx.y * 128;
    const int col0 = blockIdx.x * 128;

    if (tid < 128) s_bias[tid] = bias[col0 + tid];

    const uint32_t smb = smem_u32(smh);

    float acc[4][4][4];
#pragma unroll
    for (int a = 0; a < 4; ++a)
#pragma unroll
        for (int b = 0; b < 4; ++b)
#pragma unroll
            for (int c = 0; c < 4; ++c) acc[a][b][c] = 0.0f;

    const int NCH  = K >> 5;
    const int r_ld = tid >> 1;
    const int q0   = (tid & 1) * 2;

    const __half* srcs[4] = { Ahg, Alg, Bhg, Blg };
    const int growA = row0 + r_ld;
    const int growB = col0 + r_ld;
    const uint32_t d_sw0 = swz(r_ld, q0);
    const uint32_t d_sw1 = swz(r_ld, q0 + 1);

    auto issue = [&](int stage, int kchunk) {
        const int k0 = kchunk << 5;
        const uint32_t sbase = smb + (uint32_t)(stage * STAGEB);
#pragma unroll
        for (int p = 0; p < 4; ++p) {
            const int grow = (p < 2) ? growA : growB;
            const __half* s = srcs[p] + (size_t)grow * K + k0 + q0 * 8;
            const uint32_t db = sbase + (uint32_t)(p * PLANEB);
            cpa16(db + d_sw0, s);
            cpa16(db + d_sw1, s + 8);
        }
        asm volatile("cp.async.commit_group;" ::: "memory");
    };

    // ---- prolog ----
    issue(0, 0);
    if (NCH > 1) {
        issue(1, 1);
        asm volatile("cp.async.wait_group 1;" ::: "memory");
    } else {
        asm volatile("cp.async.wait_group 0;" ::: "memory");
    }
    __syncthreads();

    for (int i = 0; i < NCH; ++i) {
        if (i + 2 < NCH) issue((i + 2) % NSTAGE, i + 2);

        const uint32_t sb = smb + (uint32_t)((i % NSTAGE) * STAGEB);
#pragma unroll
        for (int ks = 0; ks < 2; ++ks) {
            uint32_t bh[4][2], bl[4][2];
#pragma unroll
            for (int nn = 0; nn < 2; ++nn) {
                const int rB = n_w + nn * 16 + (grp >> 1) * 8 + lr;
                const int qB = ks * 2 + (grp & 1);
                const uint32_t ab = sb + (uint32_t)(2 * PLANEB) + swz(rB, qB);
                ldsm4(bh[2 * nn][0], bh[2 * nn][1],
                      bh[2 * nn + 1][0], bh[2 * nn + 1][1], ab);
                ldsm4(bl[2 * nn][0], bl[2 * nn][1],
                      bl[2 * nn + 1][0], bl[2 * nn + 1][1],
                      ab + (uint32_t)PLANEB);
            }
#pragma unroll
            for (int mt = 0; mt < 4; ++mt) {
                uint32_t ah[4], al[4];
                const int rA = m_w + mt * 16 + (grp & 1) * 8 + lr;
                const int qA = ks * 2 + (grp >> 1);
                const uint32_t aa = sb + swz(rA, qA);
                ldsm4(ah[0], ah[1], ah[2], ah[3], aa);
                ldsm4(al[0], al[1], al[2], al[3], aa + (uint32_t)PLANEB);
#pragma unroll
                for (int nt = 0; nt < 4; ++nt) {
                    mma_f16(acc[mt][nt], ah, bh[nt]);
                    mma_f16(acc[mt][nt], ah, bl[nt]);
                    mma_f16(acc[mt][nt], al, bh[nt]);
                }
            }
        }

        if (i + 1 < NCH) {
            if (i + 2 < NCH) {
                asm volatile("cp.async.wait_group 1;" ::: "memory");
            } else {
                asm volatile("cp.async.wait_group 0;" ::: "memory");
            }
            __syncthreads();
        }
    }

    // ---- epilogue ----
#pragma unroll
    for (int mt = 0; mt < 4; ++mt) {
        int r = row0 + m_w + mt * 16 + qr;
#pragma unroll
        for (int nt = 0; nt < 4; ++nt) {
            int lc = n_w + nt * 8 + 2 * qc;
            int gc = col0 + lc;
            float2 t0, t1;
            t0.x = acc[mt][nt][0] + s_bias[lc];
            t0.y = acc[mt][nt][1] + s_bias[lc + 1];
            t1.x = acc[mt][nt][2] + s_bias[lc];
            t1.y = acc[mt][nt][3] + s_bias[lc + 1];
            if (ACT == 1) {
                t0.x = fmaxf(t0.x, 0.0f); t0.y = fmaxf(t0.y, 0.0f);
                t1.x = fmaxf(t1.x, 0.0f); t1.y = fmaxf(t1.y, 0.0f);
                __half2 h2, l2;
                split_h2(t0.x, t0.y, h2, l2);
                *reinterpret_cast<__half2*>(&Chg[(size_t)r * ldc + gc]) = h2;
                *reinterpret_cast<__half2*>(&Clg[(size_t)r * ldc + gc]) = l2;
                split_h2(t1.x, t1.y, h2, l2);
                *reinterpret_cast<__half2*>(&Chg[(size_t)(r + 8) * ldc + gc]) = h2;
                *reinterpret_cast<__half2*>(&Clg[(size_t)(r + 8) * ldc + gc]) = l2;
            } else if (ACT == 2) {
                t0.x = __fadd_rn(1e-6f, softplusf(t0.x));
                t0.y = __fadd_rn(1e-6f, softplusf(t0.y));
                t1.x = __fadd_rn(1e-6f, softplusf(t1.x));
                t1.y = __fadd_rn(1e-6f, softplusf(t1.y));
                if (gc < 2048) {
                    *reinterpret_cast<float2*>(&C [(size_t)r * 2048 + gc]) = t0;
                    *reinterpret_cast<float2*>(&C [(size_t)(r + 8) * 2048 + gc]) = t1;
                } else {
                    *reinterpret_cast<float2*>(&C2[(size_t)r * 2048 + gc - 2048]) = t0;
                    *reinterpret_cast<float2*>(&C2[(size_t)(r + 8) * 2048 + gc - 2048]) = t1;
                }
            } else {
                *reinterpret_cast<float2*>(&C[(size_t)r * ldc + gc]) = t0;
                *reinterpret_cast<float2*>(&C[(size_t)(r + 8) * ldc + gc]) = t1;
            }
        }
    }
}

// ---------------------------------------------------------------------------
// Batched weight prep: transpose + split W[K,N] fp32 -> Wh/Wl [N][K] half
// ---------------------------------------------------------------------------
struct WJobs {
    const float* W[5];
    __half* Wh[5];
    __half* Wl[5];
    int K[5], N[5], start[5];
    int njobs;
};

__global__ __launch_bounds__(256)
void prep_weights(WJobs j) {
    int b = blockIdx.x;
    int ji = 0;
#pragma unroll
    for (int s = 1; s < 5; ++s)
        if (s < j.njobs && b >= j.start[s]) ji = s;
    const float* W = j.W[ji];
    __half* Wh = j.Wh[ji];
    __half* Wl = j.Wl[ji];
    int K = j.K[ji], N = j.N[ji];
    int t = b - j.start[ji];
    int ntn = N >> 5;
    int n0 = (t % ntn) << 5, k0 = (t / ntn) << 5;

    __shared__ float s[32][33];
    int tt = threadIdx.x;
    int a = tt >> 5, bb = tt & 31;
#pragma unroll
    for (int p = 0; p < 4; ++p) {
        int k = p * 8 + a;
        s[k][bb] = W[(size_t)(k0 + k) * N + n0 + bb];
    }
    __syncthreads();
#pragma unroll
    for (int p = 0; p < 4; ++p) {
        int n = p * 8 + a;
        float v = s[bb][n];
        __half h = __float2half_rn(v);
        Wh[(size_t)(n0 + n) * K + k0 + bb] = h;
        Wl[(size_t)(n0 + n) * K + k0 + bb] =
            __float2half_rn(__fadd_rn(v, -__half2float(h)));
    }
}

// split fp32 activations -> half hi/lo planes; last block concats head bias
__global__ __launch_bounds__(256)
void split_act(const float* __restrict__ X, __half* __restrict__ Xh,
               __half* __restrict__ Xl, int n4,
               const float* __restrict__ hb1, const float* __restrict__ hb2,
               float* __restrict__ bh) {
    if ((int)blockIdx.x == (int)gridDim.x - 1) {
        int t = threadIdx.x;
        if (t < 128) bh[t] = (t < 64) ? hb1[t] : hb2[t - 64];
        return;
    }
    int t = blockIdx.x * blockDim.x + threadIdx.x;
    if (t >= n4) return;
    float4 v = reinterpret_cast<const float4*>(X)[t];
    __half2 h0, l0, h1, l1;
    split_h2(v.x, v.y, h0, l0);
    split_h2(v.z, v.w, h1, l1);
    reinterpret_cast<__half2*>(Xh)[2 * t]     = h0;
    reinterpret_cast<__half2*>(Xh)[2 * t + 1] = h1;
    reinterpret_cast<__half2*>(Xl)[2 * t]     = l0;
    reinterpret_cast<__half2*>(Xl)[2 * t + 1] = l1;
}

// ---------------------------------------------------------------------------
// Gamma sampler (reads fused head buffer g_pre[row][0:64 | 64:128])
// ---------------------------------------------------------------------------
__global__ __launch_bounds__(256)
void gamma_sampler(const float* __restrict__ pre,
                   float* __restrict__ out_la, float* __restrict__ out_lb,
                   float* __restrict__ out_z,
                   __half* __restrict__ zh, __half* __restrict__ zl) {
    int i = blockIdx.x * blockDim.x + threadIdx.x;
    if (i >= BATCHN * LATENT) return;
    int row = i >> 6, lat = i & 63;

    float al = __fadd_rn(1e-6f, softplusf(pre[row * 128 + lat]));
    float be = __fadd_rn(1e-6f, softplusf(pre[row * 128 + 64 + lat]));

    float d  = __fadd_rn(__fadd_rn(al, 1.0f), -(1.0f / 3.0f));
    float cc = __fdiv_rn(1.0f, __fsqrt_rn(__fmul_rn(9.0f, d)));

    const float LO     = -0.99999994f;
    const float SPAN_N = 2.0f;
    const float UMIN   = 1e-7f;
    const float SPAN_U = 1.0f - 1e-7f;
    const float SQRT2  = 1.41421356f;

    float eps_s = 0.0f, u_s = 0.0f, eps0 = 0.0f, u0 = 0.0f;
    bool found = false;

#pragma unroll 1
    for (int k = 0; k < KROUNDS; ++k) {
        uint32_t idx = (uint32_t)k * GAMMA_N + (uint32_t)i;
        uint32_t bn = gamma_bits(KEY_N0, KEY_N1, idx);
        uint32_t bu = gamma_bits(KEY_U0, KEY_U1, idx);

        float un = __fadd_rn(__fmul_rn(bits_to_u01(bn), SPAN_N), LO);
        un = fmaxf(LO, un);
        float eps = __fmul_rn(SQRT2, erfinv_xla(un));

        float uu = __fadd_rn(__fmul_rn(bits_to_u01(bu), SPAN_U), UMIN);
        uu = fmaxf(UMIN, uu);

        if (k == 0) { eps0 = eps; u0 = uu; }

        float v = __fadd_rn(1.0f, __fmul_rn(cc, eps));
        bool acc = false;
        if (v > 0.0f) {
            float e2 = __fmul_rn(eps, eps);
            float squeeze = __fadd_rn(1.0f, -__fmul_rn(__fmul_rn(0.0331f, e2), e2));
            if (uu < squeeze) {
                acc = true;
            } else {
                float v3 = __fmul_rn(__fmul_rn(v, v), v);
                float inner = __fadd_rn(__fadd_rn(1.0f, -v3), logf(v3));
                float rhs = __fadd_rn(__fmul_rn(__fmul_rn(0.5f, eps), eps),
                                      __fmul_rn(d, inner));
                if (logf(uu) < rhs) acc = true;
            }
        }
        if (acc) { eps_s = eps; u_s = uu; found = true; break; }
    }
    if (!found) { eps_s = eps0; u_s = u0; }

    float v1 = __fadd_rn(1.0f, __fmul_rn(cc, eps_s));
    float vs = __fmul_rn(v1, __fmul_rn(v1, v1));
    float t1 = logf(__fadd_rn(__fmul_rn(d, vs), 1e-6f));
    float t2 = __fdiv_rn(logf(__fadd_rn(u_s, 1e-6f)), __fadd_rn(al, 1e-6f));
    float z  = __fdiv_rn(expf(__fadd_rn(t1, t2)), __fadd_rn(be, 1e-6f));

    out_la[i] = al;
    out_lb[i] = be;
    out_z[i]  = z;
    __half hz = __float2half_rn(z);
    zh[i] = hz;
    zl[i] = __float2half_rn(__fadd_rn(z, -__half2float(hz)));
}

// ---------------------------------------------------------------------------
// Launch
// ---------------------------------------------------------------------------
extern "C" void kernel_launch(void* const* d_in, const int* in_sizes, int n_in,
                              void* d_out, int out_size) {
    (void)in_sizes; (void)n_in; (void)out_size;

    const float* x    = (const float*)d_in[0];
    const float* f1w  = (const float*)d_in[1];
    const float* f1b  = (const float*)d_in[2];
    const float* f2w  = (const float*)d_in[3];
    const float* f2b  = (const float*)d_in[4];
    const float* f3w  = (const float*)d_in[5];
    const float* f3b  = (const float*)d_in[6];
    const float* f41w = (const float*)d_in[7];
    const float* f41b = (const float*)d_in[8];
    const float* f42w = (const float*)d_in[9];
    const float* f42b = (const float*)d_in[10];
    const float* f4w  = (const float*)d_in[11];
    const float* f4b  = (const float*)d_in[12];
    const float* f5w  = (const float*)d_in[13];
    const float* f5b  = (const float*)d_in[14];
    const float* f6w  = (const float*)d_in[15];
    const float* f6b  = (const float*)d_in[16];
    const float* f7w  = (const float*)d_in[17];
    const float* f7b  = (const float*)d_in[18];

    float* out = (float*)d_out;
    const size_t OFF_BE = 8192ull * 2048;
    const size_t OFF_LA = 2 * OFF_BE;
    const size_t OFF_LB = OFF_LA + 524288;
    const size_t OFF_Z  = OFF_LB + 524288;

    __half *xh, *xl, *b0h, *b0l, *b1h, *b1l, *zh, *zl, *wh, *wl;
    float *pre, *bh;
    cudaGetSymbolAddress((void**)&xh,  g_xh);
    cudaGetSymbolAddress((void**)&xl,  g_xl);
    cudaGetSymbolAddress((void**)&b0h, g_b0h);
    cudaGetSymbolAddress((void**)&b0l, g_b0l);
    cudaGetSymbolAddress((void**)&b1h, g_b1h);
    cudaGetSymbolAddress((void**)&b1l, g_b1l);
    cudaGetSymbolAddress((void**)&zh,  g_zh);
    cudaGetSymbolAddress((void**)&zl,  g_zl);
    cudaGetSymbolAddress((void**)&wh,  g_wh);
    cudaGetSymbolAddress((void**)&wl,  g_wl);
    cudaGetSymbolAddress((void**)&pre, g_pre);
    cudaGetSymbolAddress((void**)&bh,  g_bh);

    constexpr int DYN = NSTAGE * STAGEB;   // 98304 bytes
    cudaFuncSetAttribute(mma_gemm<0>, cudaFuncAttributeMaxDynamicSharedMemorySize, DYN);
    cudaFuncSetAttribute(mma_gemm<1>, cudaFuncAttributeMaxDynamicSharedMemorySize, DYN);
    cudaFuncSetAttribute(mma_gemm<2>, cudaFuncAttributeMaxDynamicSharedMemorySize, DYN);

    // ---- prep: two batched transpose+split launches, then split_act ----
    // tiles per layer: (N/32)*(K/32)
    WJobs ja = {};
    ja.njobs = 5;
    ja.W[0] = f1w;  ja.Wh[0] = wh + OW1; ja.Wl[0] = wl + OW1; ja.K[0] = 2048; ja.N[0] = 1024; ja.start[0] = 0;      // 2048
    ja.W[1] = f2w;  ja.Wh[1] = wh + OW2; ja.Wl[1] = wl + OW2; ja.K[1] = 1024; ja.N[1] = 1024; ja.start[1] = 2048;   // 1024
    ja.W[2] = f3w;  ja.Wh[2] = wh + OW3; ja.Wl[2] = wl + OW3; ja.K[2] = 1024; ja.N[2] = 2048; ja.start[2] = 3072;   // 2048
    ja.W[3] = f41w; ja.Wh[3] = wh + OWH; ja.Wl[3] = wl + OWH; ja.K[3] = 2048; ja.N[3] = 64;   ja.start[3] = 5120;   // 128
    ja.W[4] = f42w; ja.Wh[4] = wh + OWH + 64 * 2048; ja.Wl[4] = wl + OWH + 64 * 2048;
    ja.K[4] = 2048; ja.N[4] = 64; ja.start[4] = 5248;                                                               // 128
    prep_weights<<<5376, 256>>>(ja);

    WJobs jb = {};
    jb.njobs = 4;
    jb.W[0] = f4w; jb.Wh[0] = wh + OW4; jb.Wl[0] = wl + OW4; jb.K[0] = 64;   jb.N[0] = 2048; jb.start[0] = 0;       // 128
    jb.W[1] = f5w; jb.Wh[1] = wh + OW5; jb.Wl[1] = wl + OW5; jb.K[1] = 2048; jb.N[1] = 1024; jb.start[1] = 128;     // 2048
    jb.W[2] = f6w; jb.Wh[2] = wh + OW6; jb.Wl[2] = wl + OW6; jb.K[2] = 1024; jb.N[2] = 1024; jb.start[2] = 2176;    // 1024
    jb.W[3] = f7w; jb.Wh[3] = wh + OW7; jb.Wl[3] = wl + OW7; jb.K[3] = 1024; jb.N[3] = 4096; jb.start[3] = 3200;    // 4096
    prep_weights<<<7296, 256>>>(jb);

    split_act<<<(8192 * 2048 / 4) / 256 + 1, 256>>>(x, xh, xl, 8192 * 2048 / 4,
                                                    f41b, f42b, bh);

    // ---- encoder (launch idx 3,4,5 — ncu -s 5 captures fc3) ----
    mma_gemm<1><<<dim3( 8, 64), 256, DYN>>>(xh,  xl,  wh + OW1, wl + OW1, f1b, b0h, b0l, nullptr, nullptr, 2048, 1024);
    mma_gemm<1><<<dim3( 8, 64), 256, DYN>>>(b0h, b0l, wh + OW2, wl + OW2, f2b, b1h, b1l, nullptr, nullptr, 1024, 1024);
    mma_gemm<1><<<dim3(16, 64), 256, DYN>>>(b1h, b1l, wh + OW3, wl + OW3, f3b, b0h, b0l, nullptr, nullptr, 1024, 2048);
    // fused heads: N=128 (cols 0-63 = fc41, 64-127 = fc42) -> fp32 pre
    mma_gemm<0><<<dim3( 1, 64), 256, DYN>>>(b0h, b0l, wh + OWH, wl + OWH, bh, nullptr, nullptr, pre, nullptr, 2048, 128);
    // ---- gamma reparameterization ----
    gamma_sampler<<<(BATCHN * LATENT) / 256, 256>>>(
        pre, out + OFF_LA, out + OFF_LB, out + OFF_Z, zh, zl);
    // ---- decoder ----
    mma_gemm<1><<<dim3(16, 64), 256, DYN>>>(zh,  zl,  wh + OW4, wl + OW4, f4b, b1h, b1l, nullptr, nullptr, 64, 2048);
    mma_gemm<1><<<dim3( 8, 64), 256, DYN>>>(b1h, b1l, wh + OW5, wl + OW5, f5b, b0h, b0l, nullptr, nullptr, 2048, 1024);
    mma_gemm<1><<<dim3( 8, 64), 256, DYN>>>(b0h, b0l, wh + OW6, wl + OW6, f6b, b1h, b1l, nullptr, nullptr, 1024, 1024);
    // fc7 with fused softplus-split epilogue -> fp32 outputs
    mma_gemm<2><<<dim3(32, 64), 256, DYN>>>(b1h, b1l, wh + OW7, wl + OW7, f7b, nullptr, nullptr, out, out + OFF_BE, 1024, 2048);
}